// round 2
// baseline (speedup 1.0000x reference)
#include <cuda_runtime.h>
#include <math.h>

// Problem dims
#define Vv 32000
#define Ee 512
#define Hh 512
#define Bb 16
#define Tt 128
#define Ss 512

constexpr int BT   = Bb * Tt;          // 2048
constexpr int G4H  = 4 * Hh;           // 2048
constexpr int KIN  = Ee + Hh;          // 1024 (lstm_input width)
constexpr int AIN  = 2 * Hh + Ee;      // 1536 (attention_input width)
constexpr long OUT0 = (long)BT * Vv;         // 65,536,000
constexpr long OUT1 = (long)BT * AIN;        // 3,145,728
constexpr long OUT2 = BT;                    // 2,048

// ---------------- scratch (device globals; no allocations allowed) -------
__device__ float g_lstm_in[BT * KIN];     // [B,T,H+E]  (context | emb)
__device__ float g_Gx[BT * G4H];          // precomputed x-part of gates (+bias)
__device__ float g_WhhT[Hh * G4H];        // W_hh transposed: [s][j]
__device__ float g_bsum[G4H];             // b_ih + b_hh
__device__ float g_hbuf[2][Bb * Hh];      // double-buffered hidden state
__device__ float g_cbuf[Bb * Hh];         // cell state
__device__ float g_lohtb[BT * 1024];      // cols 0..511 lstm_output | 512..1023 h_t_bar
__device__ float g_enc[Bb * Ss * Hh];     // direction-summed encoder outputs
__device__ float g_attn_in[BT * AIN];     // concat(lstm_output, lstm_input)
__device__ float g_att[BT * Ss];          // attention logits -> softmax (in place)
__device__ float g_albuf[BT * Hh];        // pre-sigmoid align
__device__ float g_outpre[BT * Hh];       // lstm_output + h_t_bar * aligned

// ---------------- small prep kernels -------------------------------------

__global__ void k_transpose_whh(const float* __restrict__ W_hh) {
    int i = blockIdx.x * 256 + threadIdx.x;           // over 2048*512
    if (i < G4H * Hh) {
        int j = i / Hh, s = i % Hh;
        g_WhhT[s * G4H + j] = W_hh[i];
    }
}

__global__ void k_bsum(const float* __restrict__ b_ih, const float* __restrict__ b_hh) {
    int i = blockIdx.x * 256 + threadIdx.x;
    if (i < G4H) g_bsum[i] = b_ih[i] + b_hh[i];
}

__global__ void k_init_state(const float* __restrict__ h0, const float* __restrict__ c0) {
    int i = blockIdx.x * 256 + threadIdx.x;
    if (i < Bb * Hh) { g_hbuf[0][i] = h0[i]; g_cbuf[i] = c0[i]; }
}

__global__ void k_enc(const float* __restrict__ eo) {
    int i = blockIdx.x * 256 + threadIdx.x;           // over B*S*H
    const long BSH = (long)Bb * Ss * Hh;
    if (i < BSH) g_enc[i] = eo[i] + eo[BSH + i];
}

__global__ void k_lstm_input(const int* __restrict__ x,
                             const float* __restrict__ h0,
                             const float* __restrict__ c0,
                             const float* __restrict__ emb) {
    int i = blockIdx.x * 256 + threadIdx.x;           // over BT*KIN
    if (i >= BT * KIN) return;
    int bt = i / KIN, c = i % KIN;
    int b = bt / Tt;
    float v;
    if (c < Hh) {
        v = h0[b * Hh + c] + c0[b * Hh + c];          // context (from initial state)
    } else {
        int tok = x[bt];
        v = emb[(long)tok * Ee + (c - Hh)];           // emb row 0 is already 0 (pad)
    }
    g_lstm_in[i] = v;
}

// ---------------- generic tiled SGEMM (64x64x16, 4x4 per thread) ---------
// C[z][m,n] = sum_k A[z][m,k] * B'[k,n] + bias[n]
// TB=false: B stored [K,N] row-major (ldb = row stride)
// TB=true : B stored [N,K] row-major (C = A @ B^T)
template<bool TB>
__global__ void sgemm_k(const float* __restrict__ A, int lda, long sA,
                        const float* __restrict__ Bm, int ldb, long sB,
                        const float* __restrict__ bias,
                        float* __restrict__ C, int ldc, long sC,
                        int M, int N, int K) {
    __shared__ float As[16][64];
    __shared__ float Bs[16][65];
    long z = blockIdx.z;
    A += z * sA; Bm += z * sB; C += z * sC;
    int m0 = blockIdx.y * 64, n0 = blockIdx.x * 64;
    int tx = threadIdx.x & 15, ty = threadIdx.x >> 4;
    float acc[4][4] = {};
    for (int k0 = 0; k0 < K; k0 += 16) {
        #pragma unroll
        for (int i = 0; i < 4; i++) {
            int idx = threadIdx.x + i * 256;
            int mm = idx >> 4, kk = idx & 15;
            As[kk][mm] = A[(long)(m0 + mm) * lda + (k0 + kk)];
        }
        #pragma unroll
        for (int i = 0; i < 4; i++) {
            int idx = threadIdx.x + i * 256;
            if (TB) {
                int nn = idx >> 4, kk = idx & 15;
                Bs[kk][nn] = Bm[(long)(n0 + nn) * ldb + (k0 + kk)];
            } else {
                int kk = idx >> 6, nn = idx & 63;
                Bs[kk][nn] = Bm[(long)(k0 + kk) * ldb + (n0 + nn)];
            }
        }
        __syncthreads();
        #pragma unroll
        for (int kk = 0; kk < 16; kk++) {
            float a[4], b[4];
            #pragma unroll
            for (int i = 0; i < 4; i++) a[i] = As[kk][ty * 4 + i];
            #pragma unroll
            for (int j = 0; j < 4; j++) b[j] = Bs[kk][tx * 4 + j];
            #pragma unroll
            for (int i = 0; i < 4; i++)
                #pragma unroll
                for (int j = 0; j < 4; j++)
                    acc[i][j] += a[i] * b[j];
        }
        __syncthreads();
    }
    #pragma unroll
    for (int i = 0; i < 4; i++) {
        int m = m0 + ty * 4 + i;
        #pragma unroll
        for (int j = 0; j < 4; j++) {
            int n = n0 + tx * 4 + j;
            C[(long)m * ldc + n] = acc[i][j] + (bias ? bias[n] : 0.0f);
        }
    }
}

// ---------------- LSTM recurrence step -----------------------------------
// grid: 128 blocks = (b in 0..15) x (q in 0..7); 256 threads = 4 gates x 64 k
__global__ void lstm_step_k(int t, const int* __restrict__ xlen) {
    __shared__ float hs[Hh];
    __shared__ float gs[4][64];
    int b = blockIdx.x >> 3;
    int q = blockIdx.x & 7;
    const float* hin = g_hbuf[t & 1] + b * Hh;
    for (int i = threadIdx.x; i < Hh; i += 256) hs[i] = hin[i];
    __syncthreads();
    int g  = threadIdx.x >> 6;
    int kk = threadIdx.x & 63;
    int k  = q * 64 + kk;
    int j  = g * Hh + k;
    float acc = g_Gx[(long)(b * Tt + t) * G4H + j];   // x-part + bias, precomputed
    const float* w = g_WhhT + j;
    #pragma unroll 8
    for (int s = 0; s < Hh; s++) acc += hs[s] * w[(long)s * G4H];
    gs[g][kk] = acc;
    __syncthreads();
    if (g == 0) {
        float iv = 1.0f / (1.0f + __expf(-gs[0][kk]));
        float fv = 1.0f / (1.0f + __expf(-gs[1][kk]));
        float gg = tanhf(gs[2][kk]);
        float ov = 1.0f / (1.0f + __expf(-gs[3][kk]));
        float cold = g_cbuf[b * Hh + k];
        float cn = fv * cold + iv * gg;
        float hn = ov * tanhf(cn);
        bool valid = (t < xlen[b]);
        g_cbuf[b * Hh + k]            = valid ? cn : cold;
        g_hbuf[(t + 1) & 1][b * Hh + k] = valid ? hn : hs[k];
        g_lohtb[(long)(b * Tt + t) * 1024 + k] = valid ? hn : 0.0f;
    }
}

// ---------------- attention input build ----------------------------------
__global__ void k_attn_in() {
    int i = blockIdx.x * 256 + threadIdx.x;           // over BT*AIN
    if (i >= BT * AIN) return;
    int bt = i / AIN, c = i % AIN;
    float v;
    if (c < Hh) v = g_lohtb[(long)bt * 1024 + c];                 // lstm_output
    else        v = g_lstm_in[(long)bt * KIN + (c - Hh)];          // context|emb
    g_attn_in[i] = v;
}

// ---------------- row softmax over S=512 (256 threads/row) ----------------
__global__ void softmax_k() {
    __shared__ float red[8];
    float* p = g_att + (long)blockIdx.x * Ss;
    int tid = threadIdx.x;
    float m = -1e30f;
    for (int i = tid; i < Ss; i += 256) m = fmaxf(m, p[i]);
    #pragma unroll
    for (int o = 16; o; o >>= 1) m = fmaxf(m, __shfl_xor_sync(~0u, m, o));
    if ((tid & 31) == 0) red[tid >> 5] = m;
    __syncthreads();
    if (tid == 0) { float v = red[0]; for (int i = 1; i < 8; i++) v = fmaxf(v, red[i]); red[0] = v; }
    __syncthreads();
    m = red[0];
    __syncthreads();
    float s = 0.0f;
    for (int i = tid; i < Ss; i += 256) { float e = __expf(p[i] - m); p[i] = e; s += e; }
    #pragma unroll
    for (int o = 16; o; o >>= 1) s += __shfl_xor_sync(~0u, s, o);
    if ((tid & 31) == 0) red[tid >> 5] = s;
    __syncthreads();
    if (tid == 0) { float v = 0.0f; for (int i = 0; i < 8; i++) v += red[i]; red[0] = v; }
    __syncthreads();
    float inv = 1.0f / red[0];
    for (int i = tid; i < Ss; i += 256) p[i] *= inv;
}

// ---------------- combine: out_pre = lo + htb * sigmoid(align) -----------
__global__ void k_combine(const float* __restrict__ b_align_unused) {
    int i = blockIdx.x * 256 + threadIdx.x;           // over BT*H
    if (i >= BT * Hh) return;
    int m = i / Hh, n = i % Hh;
    float al = 1.0f / (1.0f + __expf(-g_albuf[i]));
    g_outpre[i] = g_lohtb[(long)m * 1024 + n] + g_lohtb[(long)m * 1024 + Hh + n] * al;
}

// ---------------- output tail copies -------------------------------------
__global__ void k_copy_attn(float* __restrict__ o) {
    int i = blockIdx.x * 256 + threadIdx.x;
    if (i < BT * AIN) o[i] = g_attn_in[i];
}
__global__ void k_targets(float* __restrict__ o) {
    int i = blockIdx.x * 256 + threadIdx.x;
    if (i < BT) o[i] = (float)((Ss / Tt) * (i % Tt)); // 4*t, t=0 -> 0
}

// ---------------- host launcher ------------------------------------------
extern "C" void kernel_launch(void* const* d_in, const int* in_sizes, int n_in,
                              void* d_out, int out_size) {
    const int*   x       = (const int*)  d_in[0];
    const int*   xlen    = (const int*)  d_in[1];
    const float* h0      = (const float*)d_in[2];
    const float* c0      = (const float*)d_in[3];
    const float* eo      = (const float*)d_in[4];
    const float* emb     = (const float*)d_in[5];
    const float* W_att   = (const float*)d_in[6];
    const float* b_att   = (const float*)d_in[7];
    const float* W_ih    = (const float*)d_in[8];
    const float* W_hh    = (const float*)d_in[9];
    const float* b_ih    = (const float*)d_in[10];
    const float* b_hh    = (const float*)d_in[11];
    const float* W_align = (const float*)d_in[12];
    const float* b_align = (const float*)d_in[13];
    const float* W_out   = (const float*)d_in[14];
    const float* b_out   = (const float*)d_in[15];
    float* out = (float*)d_out;

    // symbol addresses for SGEMM arguments (lookup only; no stream work)
    void *p_lin, *p_gx, *p_lohtb, *p_enc, *p_attn, *p_att, *p_al, *p_op, *p_bsum;
    cudaGetSymbolAddress(&p_lin,   g_lstm_in);
    cudaGetSymbolAddress(&p_gx,    g_Gx);
    cudaGetSymbolAddress(&p_lohtb, g_lohtb);
    cudaGetSymbolAddress(&p_enc,   g_enc);
    cudaGetSymbolAddress(&p_attn,  g_attn_in);
    cudaGetSymbolAddress(&p_att,   g_att);
    cudaGetSymbolAddress(&p_al,    g_albuf);
    cudaGetSymbolAddress(&p_op,    g_outpre);
    cudaGetSymbolAddress(&p_bsum,  g_bsum);
    float* lin   = (float*)p_lin;   float* gx  = (float*)p_gx;
    float* lohtb = (float*)p_lohtb; float* enc = (float*)p_enc;
    float* attn  = (float*)p_attn;  float* att = (float*)p_att;
    float* albuf = (float*)p_al;    float* opre = (float*)p_op;
    float* bsum  = (float*)p_bsum;

    // prep
    k_transpose_whh<<<(G4H * Hh + 255) / 256, 256>>>(W_hh);
    k_bsum<<<(G4H + 255) / 256, 256>>>(b_ih, b_hh);
    k_init_state<<<(Bb * Hh + 255) / 256, 256>>>(h0, c0);
    k_enc<<<(Bb * Ss * Hh + 255) / 256, 256>>>(eo);
    k_lstm_input<<<(BT * KIN + 255) / 256, 256>>>(x, h0, c0, emb);

    // Gx = lstm_input @ W_ih^T + (b_ih+b_hh)   [2048 x 2048 x 1024]
    sgemm_k<true><<<dim3(G4H / 64, BT / 64, 1), 256>>>(
        lin, KIN, 0, W_ih, KIN, 0, bsum, gx, G4H, 0, BT, G4H, KIN);

    // LSTM recurrence
    for (int t = 0; t < Tt; t++)
        lstm_step_k<<<Bb * 8, 256>>>(t, xlen);

    // attention_input = concat(lstm_output, lstm_input)
    k_attn_in<<<(BT * AIN + 255) / 256, 256>>>();

    // att logits = attn_in @ W_att + b_att   [2048 x 512 x 1536]
    sgemm_k<false><<<dim3(Ss / 64, BT / 64, 1), 256>>>(
        attn, AIN, 0, W_att, Ss, 0, b_att, att, Ss, 0, BT, Ss, AIN);

    // softmax rows
    softmax_k<<<BT, 256>>>();

    // h_t_bar[b] = soft[b] @ enc[b]   (batched: 16 x [128 x 512 x 512])
    sgemm_k<false><<<dim3(Hh / 64, Tt / 64, Bb), 256>>>(
        att, Ss, (long)Tt * Ss,
        enc, Hh, (long)Ss * Hh,
        nullptr,
        lohtb + Hh, 1024, (long)Tt * 1024,
        Tt, Hh, Ss);

    // align = concat(lstm_out, h_t_bar) @ W_align + b_align  [2048 x 512 x 1024]
    sgemm_k<false><<<dim3(Hh / 64, BT / 64, 1), 256>>>(
        lohtb, 1024, 0, W_align, Hh, 0, b_align, albuf, Hh, 0, BT, Hh, 1024);

    // out_pre = lstm_out + h_t_bar * sigmoid(align)
    k_combine<<<(BT * Hh + 255) / 256, 256>>>(b_align);

    // out = out_pre @ W_out + b_out   [2048 x 32000 x 512]
    sgemm_k<false><<<dim3(Vv / 64, BT / 64, 1), 256>>>(
        opre, Hh, 0, W_out, Vv, 0, b_out, out, Vv, 0, BT, Vv, Hh);

    // tail outputs (tuple concat), if the harness expects them
    if ((long)out_size >= OUT0 + OUT1)
        k_copy_attn<<<(int)((OUT1 + 255) / 256), 256>>>(out + OUT0);
    if ((long)out_size >= OUT0 + OUT1 + OUT2)
        k_targets<<<(BT + 255) / 256, 256>>>(out + OUT0 + OUT1);
}

// round 3
// speedup vs baseline: 1.5444x; 1.5444x over previous
#include <cuda_runtime.h>
#include <math.h>

// Problem dims
#define Vv 32000
#define Ee 512
#define Hh 512
#define Bb 16
#define Tt 128
#define Ss 512

constexpr int BT   = Bb * Tt;          // 2048
constexpr int G4H  = 4 * Hh;           // 2048
constexpr int KIN  = Ee + Hh;          // 1024 (lstm_input width)
constexpr int AIN  = 2 * Hh + Ee;      // 1536 (attention_input width)
constexpr long OUT0 = (long)BT * Vv;         // 65,536,000
constexpr long OUT1 = (long)BT * AIN;        // 3,145,728
constexpr long OUT2 = BT;                    // 2,048

// ---------------- scratch (device globals; no allocations allowed) -------
__device__ float g_lstm_in[BT * KIN];     // [B,T,H+E]  (context | emb)
__device__ float g_Gx[BT * G4H];          // precomputed x-part of gates (+bias)
__device__ float g_WhhT[Hh * G4H];        // W_hh transposed: [s][j]
__device__ float g_bsum[G4H];             // b_ih + b_hh
__device__ float g_hbuf[2][Bb * Hh];      // double-buffered hidden state
__device__ float g_cbuf[Bb * Hh];         // cell state
__device__ float g_lohtb[BT * 1024];      // cols 0..511 lstm_output | 512..1023 h_t_bar
__device__ float g_enc[Bb * Ss * Hh];     // direction-summed encoder outputs
__device__ float g_attn_in[BT * AIN];     // concat(lstm_output, lstm_input)
__device__ float g_att[BT * Ss];          // attention logits -> softmax (in place)
__device__ float g_albuf[BT * Hh];        // pre-sigmoid align
__device__ float g_outpre[BT * Hh];       // lstm_output + h_t_bar * aligned

// ---------------- small prep kernels -------------------------------------

__global__ void k_transpose_whh(const float* __restrict__ W_hh) {
    int i = blockIdx.x * 256 + threadIdx.x;           // over 2048*512
    if (i < G4H * Hh) {
        int j = i / Hh, s = i % Hh;
        g_WhhT[s * G4H + j] = W_hh[i];
    }
}

__global__ void k_bsum(const float* __restrict__ b_ih, const float* __restrict__ b_hh) {
    int i = blockIdx.x * 256 + threadIdx.x;
    if (i < G4H) g_bsum[i] = b_ih[i] + b_hh[i];
}

__global__ void k_init_state(const float* __restrict__ h0, const float* __restrict__ c0) {
    int i = blockIdx.x * 256 + threadIdx.x;
    if (i < Bb * Hh) { g_hbuf[0][i] = h0[i]; g_cbuf[i] = c0[i]; }
}

__global__ void k_enc(const float* __restrict__ eo) {
    int i = blockIdx.x * 256 + threadIdx.x;           // over B*S*H
    const long BSH = (long)Bb * Ss * Hh;
    if (i < BSH) g_enc[i] = eo[i] + eo[BSH + i];
}

__global__ void k_lstm_input(const int* __restrict__ x,
                             const float* __restrict__ h0,
                             const float* __restrict__ c0,
                             const float* __restrict__ emb) {
    int i = blockIdx.x * 256 + threadIdx.x;           // over BT*KIN
    if (i >= BT * KIN) return;
    int bt = i / KIN, c = i % KIN;
    int b = bt / Tt;
    float v;
    if (c < Hh) {
        v = h0[b * Hh + c] + c0[b * Hh + c];          // context (from initial state)
    } else {
        int tok = x[bt];
        v = emb[(long)tok * Ee + (c - Hh)];           // emb row 0 is already 0 (pad)
    }
    g_lstm_in[i] = v;
}

// ---------------- fp32 tiled SGEMM (64x64x16) — used only for Gx ---------
template<bool TB>
__global__ void sgemm_k(const float* __restrict__ A, int lda, long sA,
                        const float* __restrict__ Bm, int ldb, long sB,
                        const float* __restrict__ bias,
                        float* __restrict__ C, int ldc, long sC,
                        int M, int N, int K) {
    __shared__ float As[16][64];
    __shared__ float Bs[16][65];
    long z = blockIdx.z;
    A += z * sA; Bm += z * sB; C += z * sC;
    int m0 = blockIdx.y * 64, n0 = blockIdx.x * 64;
    int tx = threadIdx.x & 15, ty = threadIdx.x >> 4;
    float acc[4][4] = {};
    for (int k0 = 0; k0 < K; k0 += 16) {
        #pragma unroll
        for (int i = 0; i < 4; i++) {
            int idx = threadIdx.x + i * 256;
            int mm = idx >> 4, kk = idx & 15;
            As[kk][mm] = A[(long)(m0 + mm) * lda + (k0 + kk)];
        }
        #pragma unroll
        for (int i = 0; i < 4; i++) {
            int idx = threadIdx.x + i * 256;
            if (TB) {
                int nn = idx >> 4, kk = idx & 15;
                Bs[kk][nn] = Bm[(long)(n0 + nn) * ldb + (k0 + kk)];
            } else {
                int kk = idx >> 6, nn = idx & 63;
                Bs[kk][nn] = Bm[(long)(k0 + kk) * ldb + (n0 + nn)];
            }
        }
        __syncthreads();
        #pragma unroll
        for (int kk = 0; kk < 16; kk++) {
            float a[4], b[4];
            #pragma unroll
            for (int i = 0; i < 4; i++) a[i] = As[kk][ty * 4 + i];
            #pragma unroll
            for (int j = 0; j < 4; j++) b[j] = Bs[kk][tx * 4 + j];
            #pragma unroll
            for (int i = 0; i < 4; i++)
                #pragma unroll
                for (int j = 0; j < 4; j++)
                    acc[i][j] += a[i] * b[j];
        }
        __syncthreads();
    }
    #pragma unroll
    for (int i = 0; i < 4; i++) {
        int m = m0 + ty * 4 + i;
        #pragma unroll
        for (int j = 0; j < 4; j++) {
            int n = n0 + tx * 4 + j;
            C[(long)m * ldc + n] = acc[i][j] + (bias ? bias[n] : 0.0f);
        }
    }
}

// ---------------- TF32 tensor-core GEMM (128x128x16, mma.sync) -----------
// C[z][m,n] = A[z] @ B[z] + bias,  A row-major [M,K], B row-major [K,N].
// Requires: M%128==0, N%128==0, K%16==0, lda/ldb/ldc multiples of 4.
__device__ __forceinline__ unsigned f2tf(float f) {
    unsigned u;
    asm("cvt.rna.tf32.f32 %0, %1;" : "=r"(u) : "f"(f));
    return u;
}

#define TFPAD 132

__global__ void __launch_bounds__(256) tgemm_k(
        const float* __restrict__ A, int lda, long sA,
        const float* __restrict__ Bm, int ldb, long sB,
        const float* __restrict__ bias,
        float* __restrict__ C, int ldc, long sC,
        int K) {
    __shared__ unsigned As[16 * TFPAD];
    __shared__ unsigned Bs[16 * TFPAD];
    long z = blockIdx.z;
    A += z * sA; Bm += z * sB; C += z * sC;
    const int m0 = blockIdx.y * 128, n0 = blockIdx.x * 128;
    const int tid = threadIdx.x;
    const int lane = tid & 31, wid = tid >> 5;
    const int warpM = wid >> 2, warpN = wid & 3;   // 2 x 4 warps
    const int gid = lane >> 2, tig = lane & 3;

    float acc[4][4][4];
    #pragma unroll
    for (int a = 0; a < 4; a++)
        #pragma unroll
        for (int b = 0; b < 4; b++)
            #pragma unroll
            for (int c = 0; c < 4; c++) acc[a][b][c] = 0.0f;

    const int NT = K / 16;
    // per-thread gmem load coords
    const int am = (tid >> 2), akq = (tid & 3);          // A: idx and idx+256 -> m, m+64
    const int bk = (tid >> 5), bnq = (tid & 31);         // B: k, k+8

    float4 ra[2], rb[2];
    // prologue: load tile 0
    #pragma unroll
    for (int i = 0; i < 2; i++) {
        ra[i] = *(const float4*)&A[(long)(m0 + am + i * 64) * lda + akq * 4];
        rb[i] = *(const float4*)&Bm[(long)(bk + i * 8) * ldb + n0 + bnq * 4];
    }

    for (int kt = 0; kt < NT; kt++) {
        // store current tile to smem (tf32-converted)
        #pragma unroll
        for (int i = 0; i < 2; i++) {
            int m = am + i * 64;
            As[(akq * 4 + 0) * TFPAD + m] = f2tf(ra[i].x);
            As[(akq * 4 + 1) * TFPAD + m] = f2tf(ra[i].y);
            As[(akq * 4 + 2) * TFPAD + m] = f2tf(ra[i].z);
            As[(akq * 4 + 3) * TFPAD + m] = f2tf(ra[i].w);
            uint4 u;
            u.x = f2tf(rb[i].x); u.y = f2tf(rb[i].y);
            u.z = f2tf(rb[i].z); u.w = f2tf(rb[i].w);
            *(uint4*)&Bs[(bk + i * 8) * TFPAD + bnq * 4] = u;
        }
        __syncthreads();
        // prefetch next tile into regs
        if (kt + 1 < NT) {
            int k0 = (kt + 1) * 16;
            #pragma unroll
            for (int i = 0; i < 2; i++) {
                ra[i] = *(const float4*)&A[(long)(m0 + am + i * 64) * lda + k0 + akq * 4];
                rb[i] = *(const float4*)&Bm[(long)(k0 + bk + i * 8) * ldb + n0 + bnq * 4];
            }
        }
        // compute on current tile
        #pragma unroll
        for (int ks = 0; ks < 2; ks++) {
            const int ko = ks * 8;
            unsigned af[4][4], bf[4][2];
            #pragma unroll
            for (int mi = 0; mi < 4; mi++) {
                int mm = warpM * 64 + mi * 16;
                af[mi][0] = As[(ko + tig) * TFPAD + mm + gid];
                af[mi][1] = As[(ko + tig) * TFPAD + mm + 8 + gid];
                af[mi][2] = As[(ko + tig + 4) * TFPAD + mm + gid];
                af[mi][3] = As[(ko + tig + 4) * TFPAD + mm + 8 + gid];
            }
            #pragma unroll
            for (int ni = 0; ni < 4; ni++) {
                int nn = warpN * 32 + ni * 8;
                bf[ni][0] = Bs[(ko + tig) * TFPAD + nn + gid];
                bf[ni][1] = Bs[(ko + tig + 4) * TFPAD + nn + gid];
            }
            #pragma unroll
            for (int mi = 0; mi < 4; mi++)
                #pragma unroll
                for (int ni = 0; ni < 4; ni++) {
                    asm volatile(
                        "mma.sync.aligned.m16n8k8.row.col.f32.tf32.tf32.f32 "
                        "{%0,%1,%2,%3}, {%4,%5,%6,%7}, {%8,%9}, {%0,%1,%2,%3};"
                        : "+f"(acc[mi][ni][0]), "+f"(acc[mi][ni][1]),
                          "+f"(acc[mi][ni][2]), "+f"(acc[mi][ni][3])
                        : "r"(af[mi][0]), "r"(af[mi][1]), "r"(af[mi][2]), "r"(af[mi][3]),
                          "r"(bf[ni][0]), "r"(bf[ni][1]));
                }
        }
        __syncthreads();
    }

    // epilogue
    #pragma unroll
    for (int mi = 0; mi < 4; mi++) {
        int r = m0 + warpM * 64 + mi * 16 + gid;
        #pragma unroll
        for (int ni = 0; ni < 4; ni++) {
            int cc = n0 + warpN * 32 + ni * 8 + tig * 2;
            float b0v = bias ? bias[cc] : 0.0f;
            float b1v = bias ? bias[cc + 1] : 0.0f;
            float2 v0, v1;
            v0.x = acc[mi][ni][0] + b0v; v0.y = acc[mi][ni][1] + b1v;
            v1.x = acc[mi][ni][2] + b0v; v1.y = acc[mi][ni][3] + b1v;
            *(float2*)&C[(long)r * ldc + cc] = v0;
            *(float2*)&C[(long)(r + 8) * ldc + cc] = v1;
        }
    }
}

// ---------------- LSTM recurrence step -----------------------------------
// grid: 128 blocks = (b in 0..15) x (q in 0..7); 256 threads = 4 gates x 64 k
__global__ void lstm_step_k(int t, const int* __restrict__ xlen) {
    __shared__ float hs[Hh];
    __shared__ float gs[4][64];
    int b = blockIdx.x >> 3;
    int q = blockIdx.x & 7;
    const float* hin = g_hbuf[t & 1] + b * Hh;
    for (int i = threadIdx.x; i < Hh; i += 256) hs[i] = hin[i];
    __syncthreads();
    int g  = threadIdx.x >> 6;
    int kk = threadIdx.x & 63;
    int k  = q * 64 + kk;
    int j  = g * Hh + k;
    float acc = g_Gx[(long)(b * Tt + t) * G4H + j];   // x-part + bias, precomputed
    const float* w = g_WhhT + j;
    #pragma unroll 8
    for (int s = 0; s < Hh; s++) acc += hs[s] * w[(long)s * G4H];
    gs[g][kk] = acc;
    __syncthreads();
    if (g == 0) {
        float iv = 1.0f / (1.0f + __expf(-gs[0][kk]));
        float fv = 1.0f / (1.0f + __expf(-gs[1][kk]));
        float gg = tanhf(gs[2][kk]);
        float ov = 1.0f / (1.0f + __expf(-gs[3][kk]));
        float cold = g_cbuf[b * Hh + k];
        float cn = fv * cold + iv * gg;
        float hn = ov * tanhf(cn);
        bool valid = (t < xlen[b]);
        g_cbuf[b * Hh + k]            = valid ? cn : cold;
        g_hbuf[(t + 1) & 1][b * Hh + k] = valid ? hn : hs[k];
        g_lohtb[(long)(b * Tt + t) * 1024 + k] = valid ? hn : 0.0f;
    }
}

// ---------------- attention input build ----------------------------------
__global__ void k_attn_in() {
    int i = blockIdx.x * 256 + threadIdx.x;           // over BT*AIN
    if (i >= BT * AIN) return;
    int bt = i / AIN, c = i % AIN;
    float v;
    if (c < Hh) v = g_lohtb[(long)bt * 1024 + c];                 // lstm_output
    else        v = g_lstm_in[(long)bt * KIN + (c - Hh)];          // context|emb
    g_attn_in[i] = v;
}

// ---------------- row softmax over S=512 (256 threads/row) ----------------
__global__ void softmax_k() {
    __shared__ float red[8];
    float* p = g_att + (long)blockIdx.x * Ss;
    int tid = threadIdx.x;
    float m = -1e30f;
    for (int i = tid; i < Ss; i += 256) m = fmaxf(m, p[i]);
    #pragma unroll
    for (int o = 16; o; o >>= 1) m = fmaxf(m, __shfl_xor_sync(~0u, m, o));
    if ((tid & 31) == 0) red[tid >> 5] = m;
    __syncthreads();
    if (tid == 0) { float v = red[0]; for (int i = 1; i < 8; i++) v = fmaxf(v, red[i]); red[0] = v; }
    __syncthreads();
    m = red[0];
    __syncthreads();
    float s = 0.0f;
    for (int i = tid; i < Ss; i += 256) { float e = __expf(p[i] - m); p[i] = e; s += e; }
    #pragma unroll
    for (int o = 16; o; o >>= 1) s += __shfl_xor_sync(~0u, s, o);
    if ((tid & 31) == 0) red[tid >> 5] = s;
    __syncthreads();
    if (tid == 0) { float v = 0.0f; for (int i = 0; i < 8; i++) v += red[i]; red[0] = v; }
    __syncthreads();
    float inv = 1.0f / red[0];
    for (int i = tid; i < Ss; i += 256) p[i] *= inv;
}

// ---------------- combine: out_pre = lo + htb * sigmoid(align) -----------
__global__ void k_combine() {
    int i = blockIdx.x * 256 + threadIdx.x;           // over BT*H
    if (i >= BT * Hh) return;
    int m = i / Hh, n = i % Hh;
    float al = 1.0f / (1.0f + __expf(-g_albuf[i]));
    g_outpre[i] = g_lohtb[(long)m * 1024 + n] + g_lohtb[(long)m * 1024 + Hh + n] * al;
}

// ---------------- output tail copies -------------------------------------
__global__ void k_copy_attn(float* __restrict__ o) {
    int i = blockIdx.x * 256 + threadIdx.x;
    if (i < BT * AIN) o[i] = g_attn_in[i];
}
__global__ void k_targets(float* __restrict__ o) {
    int i = blockIdx.x * 256 + threadIdx.x;
    if (i < BT) o[i] = (float)((Ss / Tt) * (i % Tt)); // 4*t, t=0 -> 0
}

// ---------------- host launcher ------------------------------------------
extern "C" void kernel_launch(void* const* d_in, const int* in_sizes, int n_in,
                              void* d_out, int out_size) {
    const int*   x       = (const int*)  d_in[0];
    const int*   xlen    = (const int*)  d_in[1];
    const float* h0      = (const float*)d_in[2];
    const float* c0      = (const float*)d_in[3];
    const float* eo      = (const float*)d_in[4];
    const float* emb     = (const float*)d_in[5];
    const float* W_att   = (const float*)d_in[6];
    const float* b_att   = (const float*)d_in[7];
    const float* W_ih    = (const float*)d_in[8];
    const float* W_hh    = (const float*)d_in[9];
    const float* b_ih    = (const float*)d_in[10];
    const float* b_hh    = (const float*)d_in[11];
    const float* W_align = (const float*)d_in[12];
    const float* b_align = (const float*)d_in[13];
    const float* W_out   = (const float*)d_in[14];
    const float* b_out   = (const float*)d_in[15];
    float* out = (float*)d_out;

    void *p_lin, *p_gx, *p_lohtb, *p_enc, *p_attn, *p_att, *p_al, *p_op, *p_bsum;
    cudaGetSymbolAddress(&p_lin,   g_lstm_in);
    cudaGetSymbolAddress(&p_gx,    g_Gx);
    cudaGetSymbolAddress(&p_lohtb, g_lohtb);
    cudaGetSymbolAddress(&p_enc,   g_enc);
    cudaGetSymbolAddress(&p_attn,  g_attn_in);
    cudaGetSymbolAddress(&p_att,   g_att);
    cudaGetSymbolAddress(&p_al,    g_albuf);
    cudaGetSymbolAddress(&p_op,    g_outpre);
    cudaGetSymbolAddress(&p_bsum,  g_bsum);
    float* lin   = (float*)p_lin;   float* gx  = (float*)p_gx;
    float* lohtb = (float*)p_lohtb; float* enc = (float*)p_enc;
    float* attn  = (float*)p_attn;  float* att = (float*)p_att;
    float* albuf = (float*)p_al;    float* opre = (float*)p_op;
    float* bsum  = (float*)p_bsum;

    // prep
    k_transpose_whh<<<(G4H * Hh + 255) / 256, 256>>>(W_hh);
    k_bsum<<<(G4H + 255) / 256, 256>>>(b_ih, b_hh);
    k_init_state<<<(Bb * Hh + 255) / 256, 256>>>(h0, c0);
    k_enc<<<(Bb * Ss * Hh + 255) / 256, 256>>>(eo);
    k_lstm_input<<<(BT * KIN + 255) / 256, 256>>>(x, h0, c0, emb);

    // Gx = lstm_input @ W_ih^T + (b_ih+b_hh)  — fp32 (feeds the recurrence)
    sgemm_k<true><<<dim3(G4H / 64, BT / 64, 1), 256>>>(
        lin, KIN, 0, W_ih, KIN, 0, bsum, gx, G4H, 0, BT, G4H, KIN);

    // LSTM recurrence
    for (int t = 0; t < Tt; t++)
        lstm_step_k<<<Bb * 8, 256>>>(t, xlen);

    // attention_input = concat(lstm_output, lstm_input)
    k_attn_in<<<(BT * AIN + 255) / 256, 256>>>();

    // att logits = attn_in @ W_att + b_att   [2048 x 512 x 1536]  (tf32)
    tgemm_k<<<dim3(Ss / 128, BT / 128, 1), 256>>>(
        attn, AIN, 0, W_att, Ss, 0, b_att, att, Ss, 0, AIN);

    // softmax rows
    softmax_k<<<BT, 256>>>();

    // h_t_bar[b] = soft[b] @ enc[b]   (batched 16 x [128 x 512 x 512], tf32)
    tgemm_k<<<dim3(Hh / 128, Tt / 128, Bb), 256>>>(
        att, Ss, (long)Tt * Ss,
        enc, Hh, (long)Ss * Hh,
        nullptr,
        lohtb + Hh, 1024, (long)Tt * 1024,
        Ss);

    // align = concat(lstm_out, h_t_bar) @ W_align + b_align  [2048x512x1024] (tf32)
    tgemm_k<<<dim3(Hh / 128, BT / 128, 1), 256>>>(
        lohtb, 1024, 0, W_align, Hh, 0, b_align, albuf, Hh, 0, 1024);

    // out_pre = lstm_out + h_t_bar * sigmoid(align)
    k_combine<<<(BT * Hh + 255) / 256, 256>>>();

    // out = out_pre @ W_out + b_out   [2048 x 32000 x 512]  (tf32)
    tgemm_k<<<dim3(Vv / 128, BT / 128, 1), 256>>>(
        opre, Hh, 0, W_out, Vv, 0, b_out, out, Vv, 0, Hh);

    // tail outputs (tuple concat), if the harness expects them
    if ((long)out_size >= OUT0 + OUT1)
        k_copy_attn<<<(int)((OUT1 + 255) / 256), 256>>>(out + OUT0);
    if ((long)out_size >= OUT0 + OUT1 + OUT2)
        k_targets<<<(BT + 255) / 256, 256>>>(out + OUT0 + OUT1);
}

// round 4
// speedup vs baseline: 3.7646x; 2.4377x over previous
#include <cuda_runtime.h>
#include <math.h>

// Problem dims
#define Vv 32000
#define Ee 512
#define Hh 512
#define Bb 16
#define Tt 128
#define Ss 512

constexpr int BT   = Bb * Tt;          // 2048
constexpr int G4H  = 4 * Hh;           // 2048
constexpr int KIN  = Ee + Hh;          // 1024
constexpr int AIN  = 2 * Hh + Ee;      // 1536
constexpr long OUT0 = (long)BT * Vv;
constexpr long OUT1 = (long)BT * AIN;
constexpr long OUT2 = BT;

// ---------------- scratch (device globals) --------------------------------
__device__ float g_lstm_in[BT * KIN];
__device__ float g_Gx[BT * G4H];
__device__ float g_WihT[KIN * G4H];       // W_ih transposed [KIN][4H]
__device__ float g_bsum[G4H];
__device__ float g_hbuf[2][Bb * Hh];
__device__ float g_cbuf[Bb * Hh];
__device__ float g_lohtb[BT * 1024];      // [ lstm_out | h_t_bar ]
__device__ float g_enc[Bb * Ss * Hh];
__device__ float g_attn_in[BT * AIN];
__device__ float g_att[BT * Ss];
__device__ float g_albuf[BT * Hh];
__device__ float g_outpre[BT * Hh];
__device__ int   g_bar;                   // persistent-LSTM grid barrier

// ---------------- small prep kernels --------------------------------------

__global__ void k_bsum(const float* __restrict__ b_ih, const float* __restrict__ b_hh) {
    int i = blockIdx.x * 256 + threadIdx.x;
    if (i < G4H) g_bsum[i] = b_ih[i] + b_hh[i];
}

__global__ void k_init_state(const float* __restrict__ h0, const float* __restrict__ c0) {
    int i = blockIdx.x * 256 + threadIdx.x;
    if (i == 0) g_bar = 0;
    if (i < Bb * Hh) { g_hbuf[0][i] = h0[i]; g_cbuf[i] = c0[i]; }
}

__global__ void k_enc(const float* __restrict__ eo) {
    int i = blockIdx.x * 256 + threadIdx.x;
    const long BSH = (long)Bb * Ss * Hh;
    if (i < BSH) g_enc[i] = eo[i] + eo[BSH + i];
}

__global__ void k_lstm_input(const int* __restrict__ x,
                             const float* __restrict__ h0,
                             const float* __restrict__ c0,
                             const float* __restrict__ emb) {
    int i = blockIdx.x * 256 + threadIdx.x;
    if (i >= BT * KIN) return;
    int bt = i / KIN, c = i % KIN;
    int b = bt / Tt;
    float v;
    if (c < Hh) v = h0[b * Hh + c] + c0[b * Hh + c];
    else        v = emb[(long)x[bt] * Ee + (c - Hh)];
    g_lstm_in[i] = v;
}

// tiled transpose: W_ih [4H][KIN] -> g_WihT [KIN][4H]
__global__ void k_transpose_wih(const float* __restrict__ W) {
    __shared__ float tile[32][33];
    int bx = blockIdx.x * 32, by = blockIdx.y * 32;   // bx over KIN cols, by over 4H rows
    int x = bx + threadIdx.x;
    #pragma unroll
    for (int i = 0; i < 32; i += 8)
        tile[threadIdx.y + i][threadIdx.x] = W[(long)(by + threadIdx.y + i) * KIN + x];
    __syncthreads();
    int xo = by + threadIdx.x;
    #pragma unroll
    for (int i = 0; i < 32; i += 8)
        g_WihT[(long)(bx + threadIdx.y + i) * G4H + xo] = tile[threadIdx.x][threadIdx.y + i];
}

// ---------------- TF32 helpers --------------------------------------------
__device__ __forceinline__ unsigned f2tf(float f) {
    unsigned u;
    asm("cvt.rna.tf32.f32 %0, %1;" : "=r"(u) : "f"(f));
    return u;
}
#define TFPAD 132

#define MMA_TF32(ACC, AF, B0, B1)                                              \
    asm volatile(                                                              \
        "mma.sync.aligned.m16n8k8.row.col.f32.tf32.tf32.f32 "                  \
        "{%0,%1,%2,%3}, {%4,%5,%6,%7}, {%8,%9}, {%0,%1,%2,%3};"                \
        : "+f"((ACC)[0]), "+f"((ACC)[1]), "+f"((ACC)[2]), "+f"((ACC)[3])       \
        : "r"((AF)[0]), "r"((AF)[1]), "r"((AF)[2]), "r"((AF)[3]),              \
          "r"(B0), "r"(B1))

// ---------------- TF32 GEMM, 128x128x16, double-buffered smem -------------
// C[z] = A[z] @ B[z] + bias; A [M,K] row-major, B [K,N] row-major.
__global__ void __launch_bounds__(256) tgemm_k(
        const float* __restrict__ A, int lda, long sA,
        const float* __restrict__ Bm, int ldb, long sB,
        const float* __restrict__ bias,
        float* __restrict__ C, int ldc, long sC,
        int K) {
    __shared__ unsigned As[2][16 * TFPAD];
    __shared__ unsigned Bs[2][16 * TFPAD];
    long z = blockIdx.z;
    A += z * sA; Bm += z * sB; C += z * sC;
    const int m0 = blockIdx.y * 128, n0 = blockIdx.x * 128;
    const int tid = threadIdx.x;
    const int lane = tid & 31, wid = tid >> 5;
    const int warpM = wid >> 2, warpN = wid & 3;
    const int gid = lane >> 2, tig = lane & 3;
    const int am = tid >> 2, akq = tid & 3;
    const int bk = tid >> 5, bnq = tid & 31;

    float acc[4][4][4] = {};
    const int NT = K / 16;

    float4 ra[2], rb[2];
    // prologue: tile 0 -> buf 0
    #pragma unroll
    for (int i = 0; i < 2; i++) {
        ra[i] = *(const float4*)&A[(long)(m0 + am + i * 64) * lda + akq * 4];
        rb[i] = *(const float4*)&Bm[(long)(bk + i * 8) * ldb + n0 + bnq * 4];
    }
    #pragma unroll
    for (int i = 0; i < 2; i++) {
        int m = am + i * 64;
        As[0][(akq * 4 + 0) * TFPAD + m] = f2tf(ra[i].x);
        As[0][(akq * 4 + 1) * TFPAD + m] = f2tf(ra[i].y);
        As[0][(akq * 4 + 2) * TFPAD + m] = f2tf(ra[i].z);
        As[0][(akq * 4 + 3) * TFPAD + m] = f2tf(ra[i].w);
        uint4 u; u.x = f2tf(rb[i].x); u.y = f2tf(rb[i].y); u.z = f2tf(rb[i].z); u.w = f2tf(rb[i].w);
        *(uint4*)&Bs[0][(bk + i * 8) * TFPAD + bnq * 4] = u;
    }
    __syncthreads();
    if (NT > 1) {
        #pragma unroll
        for (int i = 0; i < 2; i++) {
            ra[i] = *(const float4*)&A[(long)(m0 + am + i * 64) * lda + 16 + akq * 4];
            rb[i] = *(const float4*)&Bm[(long)(16 + bk + i * 8) * ldb + n0 + bnq * 4];
        }
    }

    for (int kt = 0; kt < NT; kt++) {
        const unsigned* Ac = As[kt & 1];
        const unsigned* Bc = Bs[kt & 1];
        #pragma unroll
        for (int ks = 0; ks < 2; ks++) {
            const int ko = ks * 8;
            unsigned af[4][4], bf[4][2];
            #pragma unroll
            for (int mi = 0; mi < 4; mi++) {
                int mm = warpM * 64 + mi * 16;
                af[mi][0] = Ac[(ko + tig) * TFPAD + mm + gid];
                af[mi][1] = Ac[(ko + tig) * TFPAD + mm + 8 + gid];
                af[mi][2] = Ac[(ko + tig + 4) * TFPAD + mm + gid];
                af[mi][3] = Ac[(ko + tig + 4) * TFPAD + mm + 8 + gid];
            }
            #pragma unroll
            for (int ni = 0; ni < 4; ni++) {
                int nn = warpN * 32 + ni * 8;
                bf[ni][0] = Bc[(ko + tig) * TFPAD + nn + gid];
                bf[ni][1] = Bc[(ko + tig + 4) * TFPAD + nn + gid];
            }
            #pragma unroll
            for (int mi = 0; mi < 4; mi++)
                #pragma unroll
                for (int ni = 0; ni < 4; ni++)
                    MMA_TF32(acc[mi][ni], af[mi], bf[ni][0], bf[ni][1]);
        }
        if (kt + 1 < NT) {
            unsigned* An = As[(kt + 1) & 1];
            unsigned* Bn = Bs[(kt + 1) & 1];
            #pragma unroll
            for (int i = 0; i < 2; i++) {
                int m = am + i * 64;
                An[(akq * 4 + 0) * TFPAD + m] = f2tf(ra[i].x);
                An[(akq * 4 + 1) * TFPAD + m] = f2tf(ra[i].y);
                An[(akq * 4 + 2) * TFPAD + m] = f2tf(ra[i].z);
                An[(akq * 4 + 3) * TFPAD + m] = f2tf(ra[i].w);
                uint4 u; u.x = f2tf(rb[i].x); u.y = f2tf(rb[i].y); u.z = f2tf(rb[i].z); u.w = f2tf(rb[i].w);
                *(uint4*)&Bn[(bk + i * 8) * TFPAD + bnq * 4] = u;
            }
            if (kt + 2 < NT) {
                int k0 = (kt + 2) * 16;
                #pragma unroll
                for (int i = 0; i < 2; i++) {
                    ra[i] = *(const float4*)&A[(long)(m0 + am + i * 64) * lda + k0 + akq * 4];
                    rb[i] = *(const float4*)&Bm[(long)(k0 + bk + i * 8) * ldb + n0 + bnq * 4];
                }
            }
        }
        __syncthreads();
    }

    #pragma unroll
    for (int mi = 0; mi < 4; mi++) {
        int r = m0 + warpM * 64 + mi * 16 + gid;
        #pragma unroll
        for (int ni = 0; ni < 4; ni++) {
            int cc = n0 + warpN * 32 + ni * 8 + tig * 2;
            float b0v = bias ? bias[cc] : 0.0f;
            float b1v = bias ? bias[cc + 1] : 0.0f;
            float2 v0, v1;
            v0.x = acc[mi][ni][0] + b0v; v0.y = acc[mi][ni][1] + b1v;
            v1.x = acc[mi][ni][2] + b0v; v1.y = acc[mi][ni][3] + b1v;
            *(float2*)&C[(long)r * ldc + cc] = v0;
            *(float2*)&C[(long)(r + 8) * ldc + cc] = v1;
        }
    }
}

// ---------------- error-compensated TF32 GEMM (3-mma, ~fp32 accuracy) -----
__global__ void __launch_bounds__(256) tgemm3_k(
        const float* __restrict__ A, int lda,
        const float* __restrict__ Bm, int ldb,
        const float* __restrict__ bias,
        float* __restrict__ C, int ldc,
        int K) {
    __shared__ unsigned Ah[16 * TFPAD], Al[16 * TFPAD];
    __shared__ unsigned Bh[16 * TFPAD], Bl[16 * TFPAD];
    const int m0 = blockIdx.y * 128, n0 = blockIdx.x * 128;
    const int tid = threadIdx.x;
    const int lane = tid & 31, wid = tid >> 5;
    const int warpM = wid >> 2, warpN = wid & 3;
    const int gid = lane >> 2, tig = lane & 3;
    const int am = tid >> 2, akq = tid & 3;
    const int bk = tid >> 5, bnq = tid & 31;

    float acc[4][4][4] = {};
    const int NT = K / 16;

    float4 ra[2], rb[2];
    #pragma unroll
    for (int i = 0; i < 2; i++) {
        ra[i] = *(const float4*)&A[(long)(m0 + am + i * 64) * lda + akq * 4];
        rb[i] = *(const float4*)&Bm[(long)(bk + i * 8) * ldb + n0 + bnq * 4];
    }

    for (int kt = 0; kt < NT; kt++) {
        #pragma unroll
        for (int i = 0; i < 2; i++) {
            int m = am + i * 64;
            float av[4] = {ra[i].x, ra[i].y, ra[i].z, ra[i].w};
            #pragma unroll
            for (int q = 0; q < 4; q++) {
                unsigned hb = f2tf(av[q]);
                float hf = __uint_as_float(hb);
                Ah[(akq * 4 + q) * TFPAD + m] = hb;
                Al[(akq * 4 + q) * TFPAD + m] = f2tf(av[q] - hf);
            }
            float bv[4] = {rb[i].x, rb[i].y, rb[i].z, rb[i].w};
            uint4 uh, ul;
            unsigned* ph = &uh.x; unsigned* pl = &ul.x;
            #pragma unroll
            for (int q = 0; q < 4; q++) {
                unsigned hb = f2tf(bv[q]);
                ph[q] = hb;
                pl[q] = f2tf(bv[q] - __uint_as_float(hb));
            }
            *(uint4*)&Bh[(bk + i * 8) * TFPAD + bnq * 4] = uh;
            *(uint4*)&Bl[(bk + i * 8) * TFPAD + bnq * 4] = ul;
        }
        __syncthreads();
        if (kt + 1 < NT) {
            int k0 = (kt + 1) * 16;
            #pragma unroll
            for (int i = 0; i < 2; i++) {
                ra[i] = *(const float4*)&A[(long)(m0 + am + i * 64) * lda + k0 + akq * 4];
                rb[i] = *(const float4*)&Bm[(long)(k0 + bk + i * 8) * ldb + n0 + bnq * 4];
            }
        }
        #pragma unroll
        for (int ks = 0; ks < 2; ks++) {
            const int ko = ks * 8;
            unsigned afh[4][4], afl[4][4], bfh[4][2], bfl[4][2];
            #pragma unroll
            for (int mi = 0; mi < 4; mi++) {
                int mm = warpM * 64 + mi * 16;
                afh[mi][0] = Ah[(ko + tig) * TFPAD + mm + gid];
                afh[mi][1] = Ah[(ko + tig) * TFPAD + mm + 8 + gid];
                afh[mi][2] = Ah[(ko + tig + 4) * TFPAD + mm + gid];
                afh[mi][3] = Ah[(ko + tig + 4) * TFPAD + mm + 8 + gid];
                afl[mi][0] = Al[(ko + tig) * TFPAD + mm + gid];
                afl[mi][1] = Al[(ko + tig) * TFPAD + mm + 8 + gid];
                afl[mi][2] = Al[(ko + tig + 4) * TFPAD + mm + gid];
                afl[mi][3] = Al[(ko + tig + 4) * TFPAD + mm + 8 + gid];
            }
            #pragma unroll
            for (int ni = 0; ni < 4; ni++) {
                int nn = warpN * 32 + ni * 8;
                bfh[ni][0] = Bh[(ko + tig) * TFPAD + nn + gid];
                bfh[ni][1] = Bh[(ko + tig + 4) * TFPAD + nn + gid];
                bfl[ni][0] = Bl[(ko + tig) * TFPAD + nn + gid];
                bfl[ni][1] = Bl[(ko + tig + 4) * TFPAD + nn + gid];
            }
            #pragma unroll
            for (int mi = 0; mi < 4; mi++)
                #pragma unroll
                for (int ni = 0; ni < 4; ni++) {
                    MMA_TF32(acc[mi][ni], afh[mi], bfl[ni][0], bfl[ni][1]);
                    MMA_TF32(acc[mi][ni], afl[mi], bfh[ni][0], bfh[ni][1]);
                    MMA_TF32(acc[mi][ni], afh[mi], bfh[ni][0], bfh[ni][1]);
                }
        }
        __syncthreads();
    }

    #pragma unroll
    for (int mi = 0; mi < 4; mi++) {
        int r = m0 + warpM * 64 + mi * 16 + gid;
        #pragma unroll
        for (int ni = 0; ni < 4; ni++) {
            int cc = n0 + warpN * 32 + ni * 8 + tig * 2;
            float b0v = bias ? bias[cc] : 0.0f;
            float b1v = bias ? bias[cc + 1] : 0.0f;
            float2 v0, v1;
            v0.x = acc[mi][ni][0] + b0v; v0.y = acc[mi][ni][1] + b1v;
            v1.x = acc[mi][ni][2] + b0v; v1.y = acc[mi][ni][3] + b1v;
            *(float2*)&C[(long)r * ldc + cc] = v0;
            *(float2*)&C[(long)(r + 8) * ldc + cc] = v1;
        }
    }
}

// ---------------- persistent LSTM (128 blocks, grid-sync per step) --------
// block q owns k-range [q*4, q*4+4); smem caches W_hh rows for its 16 gate
// outputs (4 gates x 4 k) across all 128 timesteps.
__global__ void __launch_bounds__(256) lstm_persist_k(const int* __restrict__ xlen,
                                                      const float* __restrict__ W_hh) {
    extern __shared__ float sm[];
    float* ws  = sm;            // [16][512]
    float* hs  = sm + 8192;     // [16][512]
    float* red = sm + 16384;    // [256][16] swizzled

    const int tid = threadIdx.x;
    const int k0  = blockIdx.x * 4;
    const int sc = tid >> 4, bt = (tid >> 2) & 3, jt = tid & 3;

    // load weight slice once: row r = g*4+dk  ->  W_hh[g*512 + k0+dk][:]
    {
        int r = tid >> 4, c16 = tid & 15;
        int g = r >> 2, dk = r & 3;
        const float4* src = (const float4*)&W_hh[(long)(g * 512 + k0 + dk) * 512];
        float4* dst = (float4*)&ws[r * 512];
        #pragma unroll
        for (int i = 0; i < 8; i++) dst[c16 + i * 16] = src[c16 + i * 16];
    }

    // updater state
    int ub = tid >> 2, udk = tid & 3;
    float creg = 0.0f; int xl = 0;
    if (tid < 64) {
        creg = g_cbuf[ub * 512 + k0 + udk];
        xl   = xlen[ub];
    }

    for (int t = 0; t < Tt; t++) {
        // load h into smem (L2-coherent loads: ping-pong buffer reused across steps)
        const float4* hin = (const float4*)g_hbuf[t & 1];
        {
            float4* hd = (float4*)hs;
            #pragma unroll
            for (int i = 0; i < 8; i++) hd[tid + i * 256] = __ldcg(&hin[tid + i * 256]);
        }
        float gxr[4];
        if (tid < 64) {
            #pragma unroll
            for (int g = 0; g < 4; g++)
                gxr[g] = g_Gx[(long)(ub * Tt + t) * G4H + g * 512 + k0 + udk];
        }
        __syncthreads();

        // partial dot products: tile 4b x 4j, s-slice per sc
        float acc[4][4] = {};
        #pragma unroll
        for (int i = 0; i < 8; i++) {
            int s = (sc << 2) + (i << 6);
            float4 hv[4], wv[4];
            #pragma unroll
            for (int bi = 0; bi < 4; bi++) hv[bi] = *(const float4*)&hs[(bt * 4 + bi) * 512 + s];
            #pragma unroll
            for (int ji = 0; ji < 4; ji++) wv[ji] = *(const float4*)&ws[(jt * 4 + ji) * 512 + s];
            #pragma unroll
            for (int bi = 0; bi < 4; bi++)
                #pragma unroll
                for (int ji = 0; ji < 4; ji++)
                    acc[bi][ji] += hv[bi].x * wv[ji].x + hv[bi].y * wv[ji].y +
                                   hv[bi].z * wv[ji].z + hv[bi].w * wv[ji].w;
        }
        // write partials (xor-swizzled to spread banks)
        {
            int perm = bt * 4 + jt;
            #pragma unroll
            for (int bi = 0; bi < 4; bi++)
                #pragma unroll
                for (int ji = 0; ji < 4; ji++) {
                    int o = (bt * 4 + bi) * 16 + jt * 4 + ji;
                    red[o * 16 + (sc ^ perm)] = acc[bi][ji];
                }
        }
        __syncthreads();

        if (tid < 64) {
            int k = k0 + udk;
            float gate[4];
            #pragma unroll
            for (int g = 0; g < 4; g++) {
                int o = ub * 16 + g * 4 + udk;
                int perm = (o >> 6) * 4 + ((o >> 2) & 3);
                float s = 0.0f;
                #pragma unroll
                for (int scx = 0; scx < 16; scx++) s += red[o * 16 + (scx ^ perm)];
                gate[g] = gxr[g] + s;
            }
            float iv = 1.0f / (1.0f + __expf(-gate[0]));
            float fv = 1.0f / (1.0f + __expf(-gate[1]));
            float gg = tanhf(gate[2]);
            float ov = 1.0f / (1.0f + __expf(-gate[3]));
            float cn = fv * creg + iv * gg;
            float hn = ov * tanhf(cn);
            bool valid = (t < xl);
            creg = valid ? cn : creg;
            float hold = hs[ub * 512 + k];
            float heff = valid ? hn : hold;
            __stcg(&g_hbuf[(t + 1) & 1][ub * 512 + k], heff);
            g_lohtb[(long)(ub * Tt + t) * 1024 + k] = valid ? hn : 0.0f;
            __threadfence();
        }
        __syncthreads();
        if (t + 1 < Tt) {
            if (tid == 0) {
                atomicAdd(&g_bar, 1);
                int target = 128 * (t + 1);
                while (*(volatile int*)&g_bar < target) __nanosleep(64);
                __threadfence();
            }
            __syncthreads();
        }
    }
}

// ---------------- attention input build -----------------------------------
__global__ void k_attn_in() {
    int i = blockIdx.x * 256 + threadIdx.x;
    if (i >= BT * AIN) return;
    int bt = i / AIN, c = i % AIN;
    float v;
    if (c < Hh) v = g_lohtb[(long)bt * 1024 + c];
    else        v = g_lstm_in[(long)bt * KIN + (c - Hh)];
    g_attn_in[i] = v;
}

// ---------------- row softmax over S=512 -----------------------------------
__global__ void softmax_k() {
    __shared__ float red[8];
    float* p = g_att + (long)blockIdx.x * Ss;
    int tid = threadIdx.x;
    float m = -1e30f;
    for (int i = tid; i < Ss; i += 256) m = fmaxf(m, p[i]);
    #pragma unroll
    for (int o = 16; o; o >>= 1) m = fmaxf(m, __shfl_xor_sync(~0u, m, o));
    if ((tid & 31) == 0) red[tid >> 5] = m;
    __syncthreads();
    if (tid == 0) { float v = red[0]; for (int i = 1; i < 8; i++) v = fmaxf(v, red[i]); red[0] = v; }
    __syncthreads();
    m = red[0];
    __syncthreads();
    float s = 0.0f;
    for (int i = tid; i < Ss; i += 256) { float e = __expf(p[i] - m); p[i] = e; s += e; }
    #pragma unroll
    for (int o = 16; o; o >>= 1) s += __shfl_xor_sync(~0u, s, o);
    if ((tid & 31) == 0) red[tid >> 5] = s;
    __syncthreads();
    if (tid == 0) { float v = 0.0f; for (int i = 0; i < 8; i++) v += red[i]; red[0] = v; }
    __syncthreads();
    float inv = 1.0f / red[0];
    for (int i = tid; i < Ss; i += 256) p[i] *= inv;
}

// ---------------- combine --------------------------------------------------
__global__ void k_combine() {
    int i = blockIdx.x * 256 + threadIdx.x;
    if (i >= BT * Hh) return;
    int m = i / Hh, n = i % Hh;
    float al = 1.0f / (1.0f + __expf(-g_albuf[i]));
    g_outpre[i] = g_lohtb[(long)m * 1024 + n] + g_lohtb[(long)m * 1024 + Hh + n] * al;
}

// ---------------- output tails ---------------------------------------------
__global__ void k_copy_attn(float* __restrict__ o) {
    int i = blockIdx.x * 256 + threadIdx.x;
    if (i < BT * AIN) o[i] = g_attn_in[i];
}
__global__ void k_targets(float* __restrict__ o) {
    int i = blockIdx.x * 256 + threadIdx.x;
    if (i < BT) o[i] = (float)((Ss / Tt) * (i % Tt));
}

// ---------------- host launcher --------------------------------------------
extern "C" void kernel_launch(void* const* d_in, const int* in_sizes, int n_in,
                              void* d_out, int out_size) {
    const int*   x       = (const int*)  d_in[0];
    const int*   xlen    = (const int*)  d_in[1];
    const float* h0      = (const float*)d_in[2];
    const float* c0      = (const float*)d_in[3];
    const float* eo      = (const float*)d_in[4];
    const float* emb     = (const float*)d_in[5];
    const float* W_att   = (const float*)d_in[6];
    const float* b_att   = (const float*)d_in[7];
    const float* W_ih    = (const float*)d_in[8];
    const float* W_hh    = (const float*)d_in[9];
    const float* b_ih    = (const float*)d_in[10];
    const float* b_hh    = (const float*)d_in[11];
    const float* W_align = (const float*)d_in[12];
    const float* b_align = (const float*)d_in[13];
    const float* W_out   = (const float*)d_in[14];
    const float* b_out   = (const float*)d_in[15];
    float* out = (float*)d_out;

    void *p_lin, *p_gx, *p_lohtb, *p_enc, *p_attn, *p_att, *p_al, *p_op, *p_bsum, *p_wiht;
    cudaGetSymbolAddress(&p_lin,   g_lstm_in);
    cudaGetSymbolAddress(&p_gx,    g_Gx);
    cudaGetSymbolAddress(&p_lohtb, g_lohtb);
    cudaGetSymbolAddress(&p_enc,   g_enc);
    cudaGetSymbolAddress(&p_attn,  g_attn_in);
    cudaGetSymbolAddress(&p_att,   g_att);
    cudaGetSymbolAddress(&p_al,    g_albuf);
    cudaGetSymbolAddress(&p_op,    g_outpre);
    cudaGetSymbolAddress(&p_bsum,  g_bsum);
    cudaGetSymbolAddress(&p_wiht,  g_WihT);
    float* lin   = (float*)p_lin;   float* gx   = (float*)p_gx;
    float* lohtb = (float*)p_lohtb; float* enc  = (float*)p_enc;
    float* attn  = (float*)p_attn;  float* att  = (float*)p_att;
    float* albuf = (float*)p_al;    float* opre = (float*)p_op;
    float* bsum  = (float*)p_bsum;  float* wihT = (float*)p_wiht;

    static bool attr_done = false;
    if (!attr_done) {
        cudaFuncSetAttribute(lstm_persist_k,
                             cudaFuncAttributeMaxDynamicSharedMemorySize, 84 * 1024);
        attr_done = true;
    }

    // prep
    k_bsum<<<(G4H + 255) / 256, 256>>>(b_ih, b_hh);
    k_init_state<<<(Bb * Hh + 255) / 256, 256>>>(h0, c0);
    k_enc<<<(Bb * Ss * Hh + 255) / 256, 256>>>(eo);
    k_lstm_input<<<(BT * KIN + 255) / 256, 256>>>(x, h0, c0, emb);
    k_transpose_wih<<<dim3(KIN / 32, G4H / 32), dim3(32, 8)>>>(W_ih);

    // Gx = lstm_input @ W_ih^T + (b_ih+b_hh)  — error-compensated tf32
    tgemm3_k<<<dim3(G4H / 128, BT / 128), 256>>>(
        lin, KIN, wihT, G4H, bsum, gx, G4H, KIN);

    // LSTM recurrence — persistent kernel
    lstm_persist_k<<<128, 256, (8192 + 8192 + 4096) * sizeof(float)>>>(xlen, W_hh);

    // attention_input = concat(lstm_output, lstm_input)
    k_attn_in<<<(BT * AIN + 255) / 256, 256>>>();

    // att logits = attn_in @ W_att + b_att
    tgemm_k<<<dim3(Ss / 128, BT / 128, 1), 256>>>(
        attn, AIN, 0, W_att, Ss, 0, b_att, att, Ss, 0, AIN);

    softmax_k<<<BT, 256>>>();

    // h_t_bar[b] = soft[b] @ enc[b]
    tgemm_k<<<dim3(Hh / 128, Tt / 128, Bb), 256>>>(
        att, Ss, (long)Tt * Ss,
        enc, Hh, (long)Ss * Hh,
        nullptr,
        lohtb + Hh, 1024, (long)Tt * 1024,
        Ss);

    // align
    tgemm_k<<<dim3(Hh / 128, BT / 128, 1), 256>>>(
        lohtb, 1024, 0, W_align, Hh, 0, b_align, albuf, Hh, 0, 1024);

    k_combine<<<(BT * Hh + 255) / 256, 256>>>();

    // out = out_pre @ W_out + b_out
    tgemm_k<<<dim3(Vv / 128, BT / 128, 1), 256>>>(
        opre, Hh, 0, W_out, Vv, 0, b_out, out, Vv, 0, Hh);

    if ((long)out_size >= OUT0 + OUT1)
        k_copy_attn<<<(int)((OUT1 + 255) / 256), 256>>>(out + OUT0);
    if ((long)out_size >= OUT0 + OUT1 + OUT2)
        k_targets<<<(BT + 255) / 256, 256>>>(out + OUT0 + OUT1);
}

// round 5
// speedup vs baseline: 4.1647x; 1.1063x over previous
#include <cuda_runtime.h>
#include <math.h>

// Problem dims
#define Vv 32000
#define Ee 512
#define Hh 512
#define Bb 16
#define Tt 128
#define Ss 512

constexpr int BT   = Bb * Tt;          // 2048
constexpr int G4H  = 4 * Hh;           // 2048
constexpr int KIN  = Ee + Hh;          // 1024
constexpr int AIN  = 2 * Hh + Ee;      // 1536
constexpr long OUT0 = (long)BT * Vv;
constexpr long OUT1 = (long)BT * AIN;
constexpr long OUT2 = BT;

// ---------------- scratch (device globals) --------------------------------
__device__ float g_lstm_in[BT * KIN];
__device__ float g_Gx[BT * G4H];
__device__ float g_WihT[KIN * G4H];       // W_ih transposed [KIN][4H]
__device__ float g_bsum[G4H];
__device__ float g_hbuf[2][Bb * Hh];
__device__ float g_cbuf[Bb * Hh];
__device__ float g_lohtb[BT * 1024];      // [ lstm_out | h_t_bar ]
__device__ float g_enc[Bb * Ss * Hh];
__device__ float g_attn_in[BT * AIN];
__device__ float g_att[BT * Ss];
__device__ float g_albuf[BT * Hh];
__device__ float g_outpre[BT * Hh];
__device__ int   g_bar;                   // persistent-LSTM grid barrier

// ---------------- small prep kernels --------------------------------------

__global__ void k_bsum(const float* __restrict__ b_ih, const float* __restrict__ b_hh) {
    int i = blockIdx.x * 256 + threadIdx.x;
    if (i < G4H) g_bsum[i] = b_ih[i] + b_hh[i];
}

__global__ void k_init_state(const float* __restrict__ h0, const float* __restrict__ c0) {
    int i = blockIdx.x * 256 + threadIdx.x;
    if (i == 0) g_bar = 0;
    if (i < Bb * Hh) { g_hbuf[0][i] = h0[i]; g_cbuf[i] = c0[i]; }
}

__global__ void k_enc(const float* __restrict__ eo) {
    int i = blockIdx.x * 256 + threadIdx.x;
    const long BSH = (long)Bb * Ss * Hh;
    if (i < BSH) g_enc[i] = eo[i] + eo[BSH + i];
}

__global__ void k_lstm_input(const int* __restrict__ x,
                             const float* __restrict__ h0,
                             const float* __restrict__ c0,
                             const float* __restrict__ emb) {
    int i = blockIdx.x * 256 + threadIdx.x;
    if (i >= BT * KIN) return;
    int bt = i / KIN, c = i % KIN;
    int b = bt / Tt;
    float v;
    if (c < Hh) v = h0[b * Hh + c] + c0[b * Hh + c];
    else        v = emb[(long)x[bt] * Ee + (c - Hh)];
    g_lstm_in[i] = v;
}

// tiled transpose: W_ih [4H][KIN] -> g_WihT [KIN][4H]
__global__ void k_transpose_wih(const float* __restrict__ W) {
    __shared__ float tile[32][33];
    int bx = blockIdx.x * 32, by = blockIdx.y * 32;
    int x = bx + threadIdx.x;
    #pragma unroll
    for (int i = 0; i < 32; i += 8)
        tile[threadIdx.y + i][threadIdx.x] = W[(long)(by + threadIdx.y + i) * KIN + x];
    __syncthreads();
    int xo = by + threadIdx.x;
    #pragma unroll
    for (int i = 0; i < 32; i += 8)
        g_WihT[(long)(bx + threadIdx.y + i) * G4H + xo] = tile[threadIdx.x][threadIdx.y + i];
}

// ---------------- TF32 helpers --------------------------------------------
__device__ __forceinline__ unsigned f2tf(float f) {
    unsigned u;
    asm("cvt.rna.tf32.f32 %0, %1;" : "=r"(u) : "f"(f));
    return u;
}
#define TFPAD 136           // 136 % 32 == 8 -> conflict-free fragment reads
#define BWPAD 264           // 264 % 32 == 8 (wide kernel B)

#define MMA_TF32(ACC, AF, B0, B1)                                              \
    asm volatile(                                                              \
        "mma.sync.aligned.m16n8k8.row.col.f32.tf32.tf32.f32 "                  \
        "{%0,%1,%2,%3}, {%4,%5,%6,%7}, {%8,%9}, {%0,%1,%2,%3};"                \
        : "+f"((ACC)[0]), "+f"((ACC)[1]), "+f"((ACC)[2]), "+f"((ACC)[3])       \
        : "r"((AF)[0]), "r"((AF)[1]), "r"((AF)[2]), "r"((AF)[3]),              \
          "r"(B0), "r"(B1))

// ---------------- TF32 GEMM, 128x128x16, double-buffered smem -------------
// C[z] = A[z] @ B[z] + bias; A [M,K] row-major, B [K,N] row-major.
__global__ void __launch_bounds__(256) tgemm_k(
        const float* __restrict__ A, int lda, long sA,
        const float* __restrict__ Bm, int ldb, long sB,
        const float* __restrict__ bias,
        float* __restrict__ C, int ldc, long sC,
        int K) {
    __shared__ unsigned As[2][16 * TFPAD];
    __shared__ unsigned Bs[2][16 * TFPAD];
    long z = blockIdx.z;
    A += z * sA; Bm += z * sB; C += z * sC;
    const int m0 = blockIdx.y * 128, n0 = blockIdx.x * 128;
    const int tid = threadIdx.x;
    const int lane = tid & 31, wid = tid >> 5;
    const int warpM = wid >> 2, warpN = wid & 3;
    const int gid = lane >> 2, tig = lane & 3;
    const int am = tid >> 2, akq = tid & 3;
    const int bk = tid >> 5, bnq = tid & 31;
    const int axor = akq * 8;

    float acc[4][4][4] = {};
    const int NT = K / 16;

    float4 ra[2], rb[2];
    #pragma unroll
    for (int i = 0; i < 2; i++) {
        ra[i] = *(const float4*)&A[(long)(m0 + am + i * 64) * lda + akq * 4];
        rb[i] = *(const float4*)&Bm[(long)(bk + i * 8) * ldb + n0 + bnq * 4];
    }
    #pragma unroll
    for (int i = 0; i < 2; i++) {
        int mc = (am + i * 64) ^ axor;
        As[0][(akq * 4 + 0) * TFPAD + mc] = f2tf(ra[i].x);
        As[0][(akq * 4 + 1) * TFPAD + mc] = f2tf(ra[i].y);
        As[0][(akq * 4 + 2) * TFPAD + mc] = f2tf(ra[i].z);
        As[0][(akq * 4 + 3) * TFPAD + mc] = f2tf(ra[i].w);
        uint4 u; u.x = f2tf(rb[i].x); u.y = f2tf(rb[i].y); u.z = f2tf(rb[i].z); u.w = f2tf(rb[i].w);
        *(uint4*)&Bs[0][(bk + i * 8) * TFPAD + bnq * 4] = u;
    }
    __syncthreads();
    if (NT > 1) {
        #pragma unroll
        for (int i = 0; i < 2; i++) {
            ra[i] = *(const float4*)&A[(long)(m0 + am + i * 64) * lda + 16 + akq * 4];
            rb[i] = *(const float4*)&Bm[(long)(16 + bk + i * 8) * ldb + n0 + bnq * 4];
        }
    }

    for (int kt = 0; kt < NT; kt++) {
        const unsigned* Ac = As[kt & 1];
        const unsigned* Bc = Bs[kt & 1];
        #pragma unroll
        for (int ks = 0; ks < 2; ks++) {
            const int ko = ks * 8;
            const int x0 = (ko >> 2) << 3;   // 0 or 16
            const int x1 = x0 + 8;           // 8 or 24
            unsigned af[4][4], bf[4][2];
            #pragma unroll
            for (int mi = 0; mi < 4; mi++) {
                int mm = warpM * 64 + mi * 16;
                af[mi][0] = Ac[(ko + tig) * TFPAD + ((mm + gid) ^ x0)];
                af[mi][1] = Ac[(ko + tig) * TFPAD + ((mm + 8 + gid) ^ x0)];
                af[mi][2] = Ac[(ko + tig + 4) * TFPAD + ((mm + gid) ^ x1)];
                af[mi][3] = Ac[(ko + tig + 4) * TFPAD + ((mm + 8 + gid) ^ x1)];
            }
            #pragma unroll
            for (int ni = 0; ni < 4; ni++) {
                int nn = warpN * 32 + ni * 8;
                bf[ni][0] = Bc[(ko + tig) * TFPAD + nn + gid];
                bf[ni][1] = Bc[(ko + tig + 4) * TFPAD + nn + gid];
            }
            #pragma unroll
            for (int mi = 0; mi < 4; mi++)
                #pragma unroll
                for (int ni = 0; ni < 4; ni++)
                    MMA_TF32(acc[mi][ni], af[mi], bf[ni][0], bf[ni][1]);
        }
        if (kt + 1 < NT) {
            unsigned* An = As[(kt + 1) & 1];
            unsigned* Bn = Bs[(kt + 1) & 1];
            #pragma unroll
            for (int i = 0; i < 2; i++) {
                int mc = (am + i * 64) ^ axor;
                An[(akq * 4 + 0) * TFPAD + mc] = f2tf(ra[i].x);
                An[(akq * 4 + 1) * TFPAD + mc] = f2tf(ra[i].y);
                An[(akq * 4 + 2) * TFPAD + mc] = f2tf(ra[i].z);
                An[(akq * 4 + 3) * TFPAD + mc] = f2tf(ra[i].w);
                uint4 u; u.x = f2tf(rb[i].x); u.y = f2tf(rb[i].y); u.z = f2tf(rb[i].z); u.w = f2tf(rb[i].w);
                *(uint4*)&Bn[(bk + i * 8) * TFPAD + bnq * 4] = u;
            }
            if (kt + 2 < NT) {
                int k0 = (kt + 2) * 16;
                #pragma unroll
                for (int i = 0; i < 2; i++) {
                    ra[i] = *(const float4*)&A[(long)(m0 + am + i * 64) * lda + k0 + akq * 4];
                    rb[i] = *(const float4*)&Bm[(long)(k0 + bk + i * 8) * ldb + n0 + bnq * 4];
                }
            }
        }
        __syncthreads();
    }

    #pragma unroll
    for (int mi = 0; mi < 4; mi++) {
        int r = m0 + warpM * 64 + mi * 16 + gid;
        #pragma unroll
        for (int ni = 0; ni < 4; ni++) {
            int cc = n0 + warpN * 32 + ni * 8 + tig * 2;
            float b0v = bias ? bias[cc] : 0.0f;
            float b1v = bias ? bias[cc + 1] : 0.0f;
            float2 v0, v1;
            v0.x = acc[mi][ni][0] + b0v; v0.y = acc[mi][ni][1] + b1v;
            v1.x = acc[mi][ni][2] + b0v; v1.y = acc[mi][ni][3] + b1v;
            *(float2*)&C[(long)r * ldc + cc] = v0;
            *(float2*)&C[(long)(r + 8) * ldc + cc] = v1;
        }
    }
}

// ---------------- WIDE TF32 GEMM: 128x256x16, warp tile 64x64 --------------
constexpr int SMW_A = 16 * TFPAD;   // per buffer, unsigneds
constexpr int SMW_B = 16 * BWPAD;
constexpr int WSMEM_BYTES = (2 * SMW_A + 2 * SMW_B) * 4;   // 51200

__global__ void __launch_bounds__(256) tgemm_wide_k(
        const float* __restrict__ A, int lda,
        const float* __restrict__ Bm, int ldb,
        const float* __restrict__ bias,
        float* __restrict__ C, int ldc,
        int K) {
    extern __shared__ unsigned smw[];
    unsigned* As = smw;                 // [2][SMW_A]
    unsigned* Bs = smw + 2 * SMW_A;     // [2][SMW_B]
    const int m0 = blockIdx.y * 128, n0 = blockIdx.x * 256;
    const int tid = threadIdx.x;
    const int lane = tid & 31, wid = tid >> 5;
    const int warpM = wid >> 2, warpN = wid & 3;
    const int gid = lane >> 2, tig = lane & 3;
    const int am = tid >> 2, akq = tid & 3;     // A: rows am, am+64; k = akq*4..+3
    const int bk = tid >> 6, bnq = tid & 63;    // B: rows bk+{0,4,8,12}; n = bnq*4..+3
    const int axor = akq * 8;

    float acc[4][8][4] = {};
    const int NT = K / 16;

    float4 ra[2], rb[4];
    #pragma unroll
    for (int i = 0; i < 2; i++)
        ra[i] = *(const float4*)&A[(long)(m0 + am + i * 64) * lda + akq * 4];
    #pragma unroll
    for (int i = 0; i < 4; i++)
        rb[i] = *(const float4*)&Bm[(long)(bk + i * 4) * ldb + n0 + bnq * 4];
    // store buf 0
    #pragma unroll
    for (int i = 0; i < 2; i++) {
        int mc = (am + i * 64) ^ axor;
        As[(akq * 4 + 0) * TFPAD + mc] = f2tf(ra[i].x);
        As[(akq * 4 + 1) * TFPAD + mc] = f2tf(ra[i].y);
        As[(akq * 4 + 2) * TFPAD + mc] = f2tf(ra[i].z);
        As[(akq * 4 + 3) * TFPAD + mc] = f2tf(ra[i].w);
    }
    #pragma unroll
    for (int i = 0; i < 4; i++) {
        uint4 u; u.x = f2tf(rb[i].x); u.y = f2tf(rb[i].y); u.z = f2tf(rb[i].z); u.w = f2tf(rb[i].w);
        *(uint4*)&Bs[(bk + i * 4) * BWPAD + bnq * 4] = u;
    }
    __syncthreads();
    if (NT > 1) {
        #pragma unroll
        for (int i = 0; i < 2; i++)
            ra[i] = *(const float4*)&A[(long)(m0 + am + i * 64) * lda + 16 + akq * 4];
        #pragma unroll
        for (int i = 0; i < 4; i++)
            rb[i] = *(const float4*)&Bm[(long)(16 + bk + i * 4) * ldb + n0 + bnq * 4];
    }

    for (int kt = 0; kt < NT; kt++) {
        const unsigned* Ac = As + (kt & 1) * SMW_A;
        const unsigned* Bc = Bs + (kt & 1) * SMW_B;
        #pragma unroll
        for (int ks = 0; ks < 2; ks++) {
            const int ko = ks * 8;
            const int x0 = (ko >> 2) << 3;
            const int x1 = x0 + 8;
            unsigned af[4][4], bf[8][2];
            #pragma unroll
            for (int mi = 0; mi < 4; mi++) {
                int mm = warpM * 64 + mi * 16;
                af[mi][0] = Ac[(ko + tig) * TFPAD + ((mm + gid) ^ x0)];
                af[mi][1] = Ac[(ko + tig) * TFPAD + ((mm + 8 + gid) ^ x0)];
                af[mi][2] = Ac[(ko + tig + 4) * TFPAD + ((mm + gid) ^ x1)];
                af[mi][3] = Ac[(ko + tig + 4) * TFPAD + ((mm + 8 + gid) ^ x1)];
            }
            #pragma unroll
            for (int ni = 0; ni < 8; ni++) {
                int nn = warpN * 64 + ni * 8;
                bf[ni][0] = Bc[(ko + tig) * BWPAD + nn + gid];
                bf[ni][1] = Bc[(ko + tig + 4) * BWPAD + nn + gid];
            }
            #pragma unroll
            for (int mi = 0; mi < 4; mi++)
                #pragma unroll
                for (int ni = 0; ni < 8; ni++)
                    MMA_TF32(acc[mi][ni], af[mi], bf[ni][0], bf[ni][1]);
        }
        if (kt + 1 < NT) {
            unsigned* An = As + ((kt + 1) & 1) * SMW_A;
            unsigned* Bn = Bs + ((kt + 1) & 1) * SMW_B;
            #pragma unroll
            for (int i = 0; i < 2; i++) {
                int mc = (am + i * 64) ^ axor;
                An[(akq * 4 + 0) * TFPAD + mc] = f2tf(ra[i].x);
                An[(akq * 4 + 1) * TFPAD + mc] = f2tf(ra[i].y);
                An[(akq * 4 + 2) * TFPAD + mc] = f2tf(ra[i].z);
                An[(akq * 4 + 3) * TFPAD + mc] = f2tf(ra[i].w);
            }
            #pragma unroll
            for (int i = 0; i < 4; i++) {
                uint4 u; u.x = f2tf(rb[i].x); u.y = f2tf(rb[i].y); u.z = f2tf(rb[i].z); u.w = f2tf(rb[i].w);
                *(uint4*)&Bn[(bk + i * 4) * BWPAD + bnq * 4] = u;
            }
            if (kt + 2 < NT) {
                int k0 = (kt + 2) * 16;
                #pragma unroll
                for (int i = 0; i < 2; i++)
                    ra[i] = *(const float4*)&A[(long)(m0 + am + i * 64) * lda + k0 + akq * 4];
                #pragma unroll
                for (int i = 0; i < 4; i++)
                    rb[i] = *(const float4*)&Bm[(long)(k0 + bk + i * 4) * ldb + n0 + bnq * 4];
            }
        }
        __syncthreads();
    }

    #pragma unroll
    for (int mi = 0; mi < 4; mi++) {
        int r = m0 + warpM * 64 + mi * 16 + gid;
        #pragma unroll
        for (int ni = 0; ni < 8; ni++) {
            int cc = n0 + warpN * 64 + ni * 8 + tig * 2;
            float b0v = bias ? bias[cc] : 0.0f;
            float b1v = bias ? bias[cc + 1] : 0.0f;
            float2 v0, v1;
            v0.x = acc[mi][ni][0] + b0v; v0.y = acc[mi][ni][1] + b1v;
            v1.x = acc[mi][ni][2] + b0v; v1.y = acc[mi][ni][3] + b1v;
            *(float2*)&C[(long)r * ldc + cc] = v0;
            *(float2*)&C[(long)(r + 8) * ldc + cc] = v1;
        }
    }
}

// ---------------- error-compensated TF32 GEMM (3-mma, ~fp32 accuracy) -----
__global__ void __launch_bounds__(256) tgemm3_k(
        const float* __restrict__ A, int lda,
        const float* __restrict__ Bm, int ldb,
        const float* __restrict__ bias,
        float* __restrict__ C, int ldc,
        int K) {
    __shared__ unsigned Ah[16 * TFPAD], Al[16 * TFPAD];
    __shared__ unsigned Bh[16 * TFPAD], Bl[16 * TFPAD];
    const int m0 = blockIdx.y * 128, n0 = blockIdx.x * 128;
    const int tid = threadIdx.x;
    const int lane = tid & 31, wid = tid >> 5;
    const int warpM = wid >> 2, warpN = wid & 3;
    const int gid = lane >> 2, tig = lane & 3;
    const int am = tid >> 2, akq = tid & 3;
    const int bk = tid >> 5, bnq = tid & 31;
    const int axor = akq * 8;

    float acc[4][4][4] = {};
    const int NT = K / 16;

    float4 ra[2], rb[2];
    #pragma unroll
    for (int i = 0; i < 2; i++) {
        ra[i] = *(const float4*)&A[(long)(m0 + am + i * 64) * lda + akq * 4];
        rb[i] = *(const float4*)&Bm[(long)(bk + i * 8) * ldb + n0 + bnq * 4];
    }

    for (int kt = 0; kt < NT; kt++) {
        #pragma unroll
        for (int i = 0; i < 2; i++) {
            int mc = (am + i * 64) ^ axor;
            float av[4] = {ra[i].x, ra[i].y, ra[i].z, ra[i].w};
            #pragma unroll
            for (int q = 0; q < 4; q++) {
                unsigned hb = f2tf(av[q]);
                Ah[(akq * 4 + q) * TFPAD + mc] = hb;
                Al[(akq * 4 + q) * TFPAD + mc] = f2tf(av[q] - __uint_as_float(hb));
            }
            float bv[4] = {rb[i].x, rb[i].y, rb[i].z, rb[i].w};
            uint4 uh, ul;
            unsigned* ph = &uh.x; unsigned* pl = &ul.x;
            #pragma unroll
            for (int q = 0; q < 4; q++) {
                unsigned hb = f2tf(bv[q]);
                ph[q] = hb;
                pl[q] = f2tf(bv[q] - __uint_as_float(hb));
            }
            *(uint4*)&Bh[(bk + i * 8) * TFPAD + bnq * 4] = uh;
            *(uint4*)&Bl[(bk + i * 8) * TFPAD + bnq * 4] = ul;
        }
        __syncthreads();
        if (kt + 1 < NT) {
            int k0 = (kt + 1) * 16;
            #pragma unroll
            for (int i = 0; i < 2; i++) {
                ra[i] = *(const float4*)&A[(long)(m0 + am + i * 64) * lda + k0 + akq * 4];
                rb[i] = *(const float4*)&Bm[(long)(k0 + bk + i * 8) * ldb + n0 + bnq * 4];
            }
        }
        #pragma unroll
        for (int ks = 0; ks < 2; ks++) {
            const int ko = ks * 8;
            const int x0 = (ko >> 2) << 3;
            const int x1 = x0 + 8;
            unsigned afh[4][4], afl[4][4], bfh[4][2], bfl[4][2];
            #pragma unroll
            for (int mi = 0; mi < 4; mi++) {
                int mm = warpM * 64 + mi * 16;
                afh[mi][0] = Ah[(ko + tig) * TFPAD + ((mm + gid) ^ x0)];
                afh[mi][1] = Ah[(ko + tig) * TFPAD + ((mm + 8 + gid) ^ x0)];
                afh[mi][2] = Ah[(ko + tig + 4) * TFPAD + ((mm + gid) ^ x1)];
                afh[mi][3] = Ah[(ko + tig + 4) * TFPAD + ((mm + 8 + gid) ^ x1)];
                afl[mi][0] = Al[(ko + tig) * TFPAD + ((mm + gid) ^ x0)];
                afl[mi][1] = Al[(ko + tig) * TFPAD + ((mm + 8 + gid) ^ x0)];
                afl[mi][2] = Al[(ko + tig + 4) * TFPAD + ((mm + gid) ^ x1)];
                afl[mi][3] = Al[(ko + tig + 4) * TFPAD + ((mm + 8 + gid) ^ x1)];
            }
            #pragma unroll
            for (int ni = 0; ni < 4; ni++) {
                int nn = warpN * 32 + ni * 8;
                bfh[ni][0] = Bh[(ko + tig) * TFPAD + nn + gid];
                bfh[ni][1] = Bh[(ko + tig + 4) * TFPAD + nn + gid];
                bfl[ni][0] = Bl[(ko + tig) * TFPAD + nn + gid];
                bfl[ni][1] = Bl[(ko + tig + 4) * TFPAD + nn + gid];
            }
            #pragma unroll
            for (int mi = 0; mi < 4; mi++)
                #pragma unroll
                for (int ni = 0; ni < 4; ni++) {
                    MMA_TF32(acc[mi][ni], afh[mi], bfl[ni][0], bfl[ni][1]);
                    MMA_TF32(acc[mi][ni], afl[mi], bfh[ni][0], bfh[ni][1]);
                    MMA_TF32(acc[mi][ni], afh[mi], bfh[ni][0], bfh[ni][1]);
                }
        }
        __syncthreads();
    }

    #pragma unroll
    for (int mi = 0; mi < 4; mi++) {
        int r = m0 + warpM * 64 + mi * 16 + gid;
        #pragma unroll
        for (int ni = 0; ni < 4; ni++) {
            int cc = n0 + warpN * 32 + ni * 8 + tig * 2;
            float b0v = bias ? bias[cc] : 0.0f;
            float b1v = bias ? bias[cc + 1] : 0.0f;
            float2 v0, v1;
            v0.x = acc[mi][ni][0] + b0v; v0.y = acc[mi][ni][1] + b1v;
            v1.x = acc[mi][ni][2] + b0v; v1.y = acc[mi][ni][3] + b1v;
            *(float2*)&C[(long)r * ldc + cc] = v0;
            *(float2*)&C[(long)(r + 8) * ldc + cc] = v1;
        }
    }
}

// ---------------- persistent LSTM (128 blocks, grid-sync per step) --------
__global__ void __launch_bounds__(256) lstm_persist_k(const int* __restrict__ xlen,
                                                      const float* __restrict__ W_hh) {
    extern __shared__ float sm[];
    float* ws  = sm;            // [16][512]
    float* hs  = sm + 8192;     // [16][512]
    float* red = sm + 16384;    // [256][16] swizzled

    const int tid = threadIdx.x;
    const int k0  = blockIdx.x * 4;
    const int sc = tid >> 4, bt = (tid >> 2) & 3, jt = tid & 3;

    {
        int r = tid >> 4, c16 = tid & 15;
        int g = r >> 2, dk = r & 3;
        const float4* src = (const float4*)&W_hh[(long)(g * 512 + k0 + dk) * 512];
        float4* dst = (float4*)&ws[r * 512];
        #pragma unroll
        for (int i = 0; i < 8; i++) dst[c16 + i * 16] = src[c16 + i * 16];
    }

    int ub = tid >> 2, udk = tid & 3;
    float creg = 0.0f; int xl = 0;
    if (tid < 64) {
        creg = g_cbuf[ub * 512 + k0 + udk];
        xl   = xlen[ub];
    }

    for (int t = 0; t < Tt; t++) {
        const float4* hin = (const float4*)g_hbuf[t & 1];
        {
            float4* hd = (float4*)hs;
            #pragma unroll
            for (int i = 0; i < 8; i++) hd[tid + i * 256] = __ldcg(&hin[tid + i * 256]);
        }
        float gxr[4];
        if (tid < 64) {
            #pragma unroll
            for (int g = 0; g < 4; g++)
                gxr[g] = g_Gx[(long)(ub * Tt + t) * G4H + g * 512 + k0 + udk];
        }
        __syncthreads();

        float acc[4][4] = {};
        #pragma unroll
        for (int i = 0; i < 8; i++) {
            int s = (sc << 2) + (i << 6);
            float4 hv[4], wv[4];
            #pragma unroll
            for (int bi = 0; bi < 4; bi++) hv[bi] = *(const float4*)&hs[(bt * 4 + bi) * 512 + s];
            #pragma unroll
            for (int ji = 0; ji < 4; ji++) wv[ji] = *(const float4*)&ws[(jt * 4 + ji) * 512 + s];
            #pragma unroll
            for (int bi = 0; bi < 4; bi++)
                #pragma unroll
                for (int ji = 0; ji < 4; ji++)
                    acc[bi][ji] += hv[bi].x * wv[ji].x + hv[bi].y * wv[ji].y +
                                   hv[bi].z * wv[ji].z + hv[bi].w * wv[ji].w;
        }
        {
            int perm = bt * 4 + jt;
            #pragma unroll
            for (int bi = 0; bi < 4; bi++)
                #pragma unroll
                for (int ji = 0; ji < 4; ji++) {
                    int o = (bt * 4 + bi) * 16 + jt * 4 + ji;
                    red[o * 16 + (sc ^ perm)] = acc[bi][ji];
                }
        }
        __syncthreads();

        if (tid < 64) {
            int k = k0 + udk;
            float gate[4];
            #pragma unroll
            for (int g = 0; g < 4; g++) {
                int o = ub * 16 + g * 4 + udk;
                int perm = (o >> 6) * 4 + ((o >> 2) & 3);
                float s = 0.0f;
                #pragma unroll
                for (int scx = 0; scx < 16; scx++) s += red[o * 16 + (scx ^ perm)];
                gate[g] = gxr[g] + s;
            }
            float iv = 1.0f / (1.0f + __expf(-gate[0]));
            float fv = 1.0f / (1.0f + __expf(-gate[1]));
            float gg = tanhf(gate[2]);
            float ov = 1.0f / (1.0f + __expf(-gate[3]));
            float cn = fv * creg + iv * gg;
            float hn = ov * tanhf(cn);
            bool valid = (t < xl);
            creg = valid ? cn : creg;
            float hold = hs[ub * 512 + k];
            float heff = valid ? hn : hold;
            __stcg(&g_hbuf[(t + 1) & 1][ub * 512 + k], heff);
            g_lohtb[(long)(ub * Tt + t) * 1024 + k] = valid ? hn : 0.0f;
            __threadfence();
        }
        __syncthreads();
        if (t + 1 < Tt) {
            if (tid == 0) {
                atomicAdd(&g_bar, 1);
                int target = 128 * (t + 1);
                while (*(volatile int*)&g_bar < target) __nanosleep(64);
                __threadfence();
            }
            __syncthreads();
        }
    }
}

// ---------------- attention input build (also writes output slot 1) -------
__global__ void k_attn_in(float* __restrict__ o, int write_out) {
    int i = blockIdx.x * 256 + threadIdx.x;
    if (i >= BT * AIN) return;
    int bt = i / AIN, c = i % AIN;
    float v;
    if (c < Hh) v = g_lohtb[(long)bt * 1024 + c];
    else        v = g_lstm_in[(long)bt * KIN + (c - Hh)];
    g_attn_in[i] = v;
    if (write_out) o[i] = v;
}

// ---------------- row softmax over S=512 -----------------------------------
__global__ void softmax_k() {
    __shared__ float red[8];
    float* p = g_att + (long)blockIdx.x * Ss;
    int tid = threadIdx.x;
    float m = -1e30f;
    for (int i = tid; i < Ss; i += 256) m = fmaxf(m, p[i]);
    #pragma unroll
    for (int o = 16; o; o >>= 1) m = fmaxf(m, __shfl_xor_sync(~0u, m, o));
    if ((tid & 31) == 0) red[tid >> 5] = m;
    __syncthreads();
    if (tid == 0) { float v = red[0]; for (int i = 1; i < 8; i++) v = fmaxf(v, red[i]); red[0] = v; }
    __syncthreads();
    m = red[0];
    __syncthreads();
    float s = 0.0f;
    for (int i = tid; i < Ss; i += 256) { float e = __expf(p[i] - m); p[i] = e; s += e; }
    #pragma unroll
    for (int o = 16; o; o >>= 1) s += __shfl_xor_sync(~0u, s, o);
    if ((tid & 31) == 0) red[tid >> 5] = s;
    __syncthreads();
    if (tid == 0) { float v = 0.0f; for (int i = 0; i < 8; i++) v += red[i]; red[0] = v; }
    __syncthreads();
    float inv = 1.0f / red[0];
    for (int i = tid; i < Ss; i += 256) p[i] *= inv;
}

// ---------------- combine --------------------------------------------------
__global__ void k_combine() {
    int i = blockIdx.x * 256 + threadIdx.x;
    if (i >= BT * Hh) return;
    int m = i / Hh, n = i % Hh;
    float al = 1.0f / (1.0f + __expf(-g_albuf[i]));
    g_outpre[i] = g_lohtb[(long)m * 1024 + n] + g_lohtb[(long)m * 1024 + Hh + n] * al;
}

// ---------------- output tails ---------------------------------------------
__global__ void k_targets(float* __restrict__ o) {
    int i = blockIdx.x * 256 + threadIdx.x;
    if (i < BT) o[i] = (float)((Ss / Tt) * (i % Tt));
}

// ---------------- host launcher --------------------------------------------
extern "C" void kernel_launch(void* const* d_in, const int* in_sizes, int n_in,
                              void* d_out, int out_size) {
    const int*   x       = (const int*)  d_in[0];
    const int*   xlen    = (const int*)  d_in[1];
    const float* h0      = (const float*)d_in[2];
    const float* c0      = (const float*)d_in[3];
    const float* eo      = (const float*)d_in[4];
    const float* emb     = (const float*)d_in[5];
    const float* W_att   = (const float*)d_in[6];
    const float* b_att   = (const float*)d_in[7];
    const float* W_ih    = (const float*)d_in[8];
    const float* W_hh    = (const float*)d_in[9];
    const float* b_ih    = (const float*)d_in[10];
    const float* b_hh    = (const float*)d_in[11];
    const float* W_align = (const float*)d_in[12];
    const float* b_align = (const float*)d_in[13];
    const float* W_out   = (const float*)d_in[14];
    const float* b_out   = (const float*)d_in[15];
    float* out = (float*)d_out;

    void *p_lin, *p_gx, *p_lohtb, *p_enc, *p_attn, *p_att, *p_al, *p_op, *p_bsum, *p_wiht;
    cudaGetSymbolAddress(&p_lin,   g_lstm_in);
    cudaGetSymbolAddress(&p_gx,    g_Gx);
    cudaGetSymbolAddress(&p_lohtb, g_lohtb);
    cudaGetSymbolAddress(&p_enc,   g_enc);
    cudaGetSymbolAddress(&p_attn,  g_attn_in);
    cudaGetSymbolAddress(&p_att,   g_att);
    cudaGetSymbolAddress(&p_al,    g_albuf);
    cudaGetSymbolAddress(&p_op,    g_outpre);
    cudaGetSymbolAddress(&p_bsum,  g_bsum);
    cudaGetSymbolAddress(&p_wiht,  g_WihT);
    float* lin   = (float*)p_lin;   float* gx   = (float*)p_gx;
    float* lohtb = (float*)p_lohtb; float* enc  = (float*)p_enc;
    float* attn  = (float*)p_attn;  float* att  = (float*)p_att;
    float* albuf = (float*)p_al;    float* opre = (float*)p_op;
    float* bsum  = (float*)p_bsum;  float* wihT = (float*)p_wiht;

    static bool attr_done = false;
    if (!attr_done) {
        cudaFuncSetAttribute(lstm_persist_k,
                             cudaFuncAttributeMaxDynamicSharedMemorySize, 84 * 1024);
        cudaFuncSetAttribute(tgemm_wide_k,
                             cudaFuncAttributeMaxDynamicSharedMemorySize, 64 * 1024);
        attr_done = true;
    }

    // prep
    k_bsum<<<(G4H + 255) / 256, 256>>>(b_ih, b_hh);
    k_init_state<<<(Bb * Hh + 255) / 256, 256>>>(h0, c0);
    k_enc<<<(Bb * Ss * Hh + 255) / 256, 256>>>(eo);
    k_lstm_input<<<(BT * KIN + 255) / 256, 256>>>(x, h0, c0, emb);
    k_transpose_wih<<<dim3(KIN / 32, G4H / 32), dim3(32, 8)>>>(W_ih);

    // Gx = lstm_input @ W_ih^T + (b_ih+b_hh)  — error-compensated tf32
    tgemm3_k<<<dim3(G4H / 128, BT / 128), 256>>>(
        lin, KIN, wihT, G4H, bsum, gx, G4H, KIN);

    // LSTM recurrence — persistent kernel
    lstm_persist_k<<<128, 256, (8192 + 8192 + 4096) * sizeof(float)>>>(xlen, W_hh);

    // attention_input = concat(lstm_output, lstm_input); also fills output slot 1
    int wo = ((long)out_size >= OUT0 + OUT1) ? 1 : 0;
    k_attn_in<<<(BT * AIN + 255) / 256, 256>>>(out + OUT0, wo);

    // att logits = attn_in @ W_att + b_att
    tgemm_k<<<dim3(Ss / 128, BT / 128, 1), 256>>>(
        attn, AIN, 0, W_att, Ss, 0, b_att, att, Ss, 0, AIN);

    softmax_k<<<BT, 256>>>();

    // h_t_bar[b] = soft[b] @ enc[b]
    tgemm_k<<<dim3(Hh / 128, Tt / 128, Bb), 256>>>(
        att, Ss, (long)Tt * Ss,
        enc, Hh, (long)Ss * Hh,
        nullptr,
        lohtb + Hh, 1024, (long)Tt * 1024,
        Ss);

    // align
    tgemm_k<<<dim3(Hh / 128, BT / 128, 1), 256>>>(
        lohtb, 1024, 0, W_align, Hh, 0, b_align, albuf, Hh, 0, 1024);

    k_combine<<<(BT * Hh + 255) / 256, 256>>>();

    // out = out_pre @ W_out + b_out  — wide tile 128x256
    tgemm_wide_k<<<dim3(Vv / 256, BT / 128), 256, WSMEM_BYTES>>>(
        opre, Hh, W_out, Vv, b_out, out, Vv, Hh);

    if ((long)out_size >= OUT0 + OUT1 + OUT2)
        k_targets<<<(BT + 255) / 256, 256>>>(out + OUT0 + OUT1);
}